// round 2
// baseline (speedup 1.0000x reference)
#include <cuda_runtime.h>
#include <math.h>

#define Bz   64
#define Tt   256
#define Vv   4096
#define Ee   512
#define Hh   1024
#define BT   (Bz*Tt)     // 16384
#define CAT  (Ee+Hh)     // 1536

// ---------------- static device scratch (no allocations allowed) ----------------
__device__ float    g_emb[BT * Ee];            // 32 MB   [bt][e]
__device__ float    g_pre[3u * BT * Hh];       // 192 MB  [gate][bt][n], gate 0=r,1=z,2=hbar
__device__ float    g_h[Bz * Hh];              // current hidden state [b][n]
__device__ float    g_rh[Bz * Hh];             // r * h
__device__ float    g_zz[Bz * Hh];             // z
__device__ float    g_hidden[BT * Hh];         // 64 MB   [bt][n]
__device__ unsigned g_bar[1024];               // grid-barrier counters

// ---------------- init: zero barrier counters, broadcast start -> h ----------------
__global__ void k_init(const float* __restrict__ start) {
    int i = blockIdx.x * blockDim.x + threadIdx.x;   // grid covers 65536
    if (i < Bz * Hh) g_h[i] = start[i & (Hh - 1)];
    if (i < 1024)    g_bar[i] = 0u;
}

// ---------------- embedding gather ----------------
__global__ void k_embed(const int* __restrict__ x, const float* __restrict__ wte) {
    int i  = blockIdx.x * blockDim.x + threadIdx.x;  // float4 index, total BT*Ee/4
    int bt = i >> 7;                                  // Ee/4 = 128 float4 per row
    int e4 = i & 127;
    int tok = x[bt];
    reinterpret_cast<float4*>(g_emb)[i] =
        reinterpret_cast<const float4*>(wte + (size_t)tok * Ee)[e4];
}

// ---------------- generic fp32 GEMM:  C[M,N] = A[M,K] * W[N,K]^T + bias ----------------
// tile 64x64, 256 threads, 4x4 per thread, Kt=32, k-major smem (all LDS are .128)
__global__ void __launch_bounds__(256) k_gemm(
    const float* __restrict__ A, int lda,
    const float* __restrict__ W, int ldw,
    const float* __restrict__ bias,
    float* __restrict__ C, int ldc, int K)
{
    __shared__ float As[32][64];
    __shared__ float Bs[32][64];

    const int tx = threadIdx.x & 15;       // col group
    const int ty = threadIdx.x >> 4;       // row group
    const int m0 = blockIdx.y * 64;
    const int n0 = blockIdx.x * 64;

    float acc[4][4] = {};

    for (int k0 = 0; k0 < K; k0 += 32) {
        // cooperative load: 512 float4 per tile per matrix, 2 per thread
        #pragma unroll
        for (int r = 0; r < 2; r++) {
            int q   = threadIdx.x + r * 256;
            int row = q >> 3;
            int kq  = (q & 7) << 2;
            float4 av = *reinterpret_cast<const float4*>(A + (size_t)(m0 + row) * lda + k0 + kq);
            As[kq + 0][row] = av.x; As[kq + 1][row] = av.y;
            As[kq + 2][row] = av.z; As[kq + 3][row] = av.w;
            float4 bv = *reinterpret_cast<const float4*>(W + (size_t)(n0 + row) * ldw + k0 + kq);
            Bs[kq + 0][row] = bv.x; Bs[kq + 1][row] = bv.y;
            Bs[kq + 2][row] = bv.z; Bs[kq + 3][row] = bv.w;
        }
        __syncthreads();

        #pragma unroll
        for (int kk = 0; kk < 32; kk++) {
            float4 a = *reinterpret_cast<float4*>(&As[kk][ty * 4]);
            float4 b = *reinterpret_cast<float4*>(&Bs[kk][tx * 4]);
            float av[4] = {a.x, a.y, a.z, a.w};
            float bv[4] = {b.x, b.y, b.z, b.w};
            #pragma unroll
            for (int i = 0; i < 4; i++)
                #pragma unroll
                for (int j = 0; j < 4; j++)
                    acc[i][j] = fmaf(av[i], bv[j], acc[i][j]);
        }
        __syncthreads();
    }

    #pragma unroll
    for (int i = 0; i < 4; i++) {
        int m = m0 + ty * 4 + i;
        int n = n0 + tx * 4;
        float4 o;
        o.x = acc[i][0] + bias[n + 0];
        o.y = acc[i][1] + bias[n + 1];
        o.z = acc[i][2] + bias[n + 2];
        o.w = acc[i][3] + bias[n + 3];
        *reinterpret_cast<float4*>(C + (size_t)m * ldc + n) = o;
    }
}

// ---------------- grid barrier (all blocks co-resident by construction) ----------------
__device__ __forceinline__ void gbarrier(int idx, unsigned G) {
    __syncthreads();
    if (threadIdx.x == 0) {
        __threadfence();
        unsigned a = atomicAdd(&g_bar[idx], 1u);
        if (a + 1u < G) {
            while (*reinterpret_cast<volatile unsigned*>(&g_bar[idx]) < G) { }
        }
        __threadfence();
    }
    __syncthreads();
}

// ---------------- persistent GRU scan ----------------
// grid = 128 blocks x 512 threads (co-resident on 148 SMs)
// phase1: r,z = sigmoid(pre + h @ Wg[:,E:]^T); write r*h and z
// phase2: hbar = tanh(pre + (r*h) @ Wbar[:,E:]^T); h = h + z*(hbar-h); store hidden[t]
__global__ void __launch_bounds__(512) k_scan(
    const float* __restrict__ Wr,
    const float* __restrict__ Wz,
    const float* __restrict__ Wbar)
{
    __shared__ float hs[64][32];
    __shared__ float ws[16][32];

    const int tid = threadIdx.x;
    const int g   = blockIdx.x;
    const unsigned G = gridDim.x;

    for (int t = 0; t < Tt; t++) {
        // ================= phase 1: gates r and z =================
        {
            const bool  isZ = (g >= 64);
            const int   n0  = (g & 63) * 16;
            const float* W  = isZ ? Wz : Wr;
            const float* pre = g_pre + (isZ ? (size_t)BT * Hh : (size_t)0);

            const int tx = tid & 15;       // column 0..15
            const int ty = tid >> 4;       // 0..31 -> rows 2ty, 2ty+1
            float acc0 = 0.f, acc1 = 0.f;

            for (int k0 = 0; k0 < Hh; k0 += 32) {
                int m  = tid >> 3;
                int kq = (tid & 7) << 2;
                *reinterpret_cast<float4*>(&hs[m][kq]) =
                    *reinterpret_cast<const float4*>(g_h + m * Hh + k0 + kq);
                int c  = tid >> 5;          // 0..15
                int kk = tid & 31;
                ws[c][kk] = W[(size_t)(n0 + c) * CAT + Ee + k0 + kk];
                __syncthreads();

                #pragma unroll
                for (int kk2 = 0; kk2 < 32; kk2 += 4) {
                    float4 a0 = *reinterpret_cast<float4*>(&hs[2 * ty][kk2]);
                    float4 a1 = *reinterpret_cast<float4*>(&hs[2 * ty + 1][kk2]);
                    float4 w4 = *reinterpret_cast<float4*>(&ws[tx][kk2]);
                    acc0 = fmaf(a0.x, w4.x, acc0); acc0 = fmaf(a0.y, w4.y, acc0);
                    acc0 = fmaf(a0.z, w4.z, acc0); acc0 = fmaf(a0.w, w4.w, acc0);
                    acc1 = fmaf(a1.x, w4.x, acc1); acc1 = fmaf(a1.y, w4.y, acc1);
                    acc1 = fmaf(a1.z, w4.z, acc1); acc1 = fmaf(a1.w, w4.w, acc1);
                }
                __syncthreads();
            }

            const int n = n0 + tx;
            #pragma unroll
            for (int i = 0; i < 2; i++) {
                int m = 2 * ty + i;
                float a = (i == 0) ? acc0 : acc1;
                float p = pre[(size_t)(m * Tt + t) * Hh + n];
                float gv = 1.f / (1.f + __expf(-(a + p)));
                if (!isZ) g_rh[m * Hh + n] = gv * g_h[m * Hh + n];
                else      g_zz[m * Hh + n] = gv;
            }
        }
        gbarrier(2 * t, G);

        // ================= phase 2: hbar + state update =================
        {
            const int n0 = g * 8;
            const int tx = tid & 7;        // column 0..7
            const int ty = tid >> 3;       // row 0..63
            float acc = 0.f;

            for (int k0 = 0; k0 < Hh; k0 += 32) {
                int m  = tid >> 3;
                int kq = (tid & 7) << 2;
                *reinterpret_cast<float4*>(&hs[m][kq]) =
                    *reinterpret_cast<const float4*>(g_rh + m * Hh + k0 + kq);
                if (tid < 256) {
                    int c  = tid >> 5;      // 0..7
                    int kk = tid & 31;
                    ws[c][kk] = Wbar[(size_t)(n0 + c) * CAT + Ee + k0 + kk];
                }
                __syncthreads();

                #pragma unroll
                for (int kk2 = 0; kk2 < 32; kk2 += 4) {
                    float4 a0 = *reinterpret_cast<float4*>(&hs[ty][kk2]);
                    float4 w4 = *reinterpret_cast<float4*>(&ws[tx][kk2]);
                    acc = fmaf(a0.x, w4.x, acc); acc = fmaf(a0.y, w4.y, acc);
                    acc = fmaf(a0.z, w4.z, acc); acc = fmaf(a0.w, w4.w, acc);
                }
                __syncthreads();
            }

            const int n = n0 + tx;
            const int m = ty;
            float p    = g_pre[(size_t)2 * BT * Hh + (size_t)(m * Tt + t) * Hh + n];
            float hbar = tanhf(acc + p);
            float z    = g_zz[m * Hh + n];
            float hp   = g_h[m * Hh + n];
            float hn   = fmaf(z, hbar - hp, hp);
            g_h[m * Hh + n] = hn;
            g_hidden[(size_t)(m * Tt + t) * Hh + n] = hn;
        }
        gbarrier(2 * t + 1, G);
    }
}

// ---------------- launch ----------------
extern "C" void kernel_launch(void* const* d_in, const int* in_sizes, int n_in,
                              void* d_out, int out_size)
{
    const int*   x     = (const int*)  d_in[0];
    const float* start = (const float*)d_in[1];
    const float* wte   = (const float*)d_in[2];
    const float* Wr    = (const float*)d_in[3];
    const float* br    = (const float*)d_in[4];
    const float* Wbar  = (const float*)d_in[5];
    const float* bbar  = (const float*)d_in[6];
    const float* Wz    = (const float*)d_in[7];
    const float* bz    = (const float*)d_in[8];
    const float* Whead = (const float*)d_in[9];
    const float* bhead = (const float*)d_in[10];
    float* out = (float*)d_out;

    float *p_emb, *p_pre, *p_hidden;
    cudaGetSymbolAddress((void**)&p_emb,    g_emb);
    cudaGetSymbolAddress((void**)&p_pre,    g_pre);
    cudaGetSymbolAddress((void**)&p_hidden, g_hidden);

    k_init<<<256, 256>>>(start);
    k_embed<<<(BT * Ee / 4) / 256, 256>>>(x, wte);

    // input projections (first E columns of each weight), pre[gate][bt][n]
    k_gemm<<<dim3(Hh / 64, BT / 64), 256>>>(p_emb, Ee, Wr,   CAT, br,   p_pre,                Hh, Ee);
    k_gemm<<<dim3(Hh / 64, BT / 64), 256>>>(p_emb, Ee, Wz,   CAT, bz,   p_pre + (size_t)BT*Hh, Hh, Ee);
    k_gemm<<<dim3(Hh / 64, BT / 64), 256>>>(p_emb, Ee, Wbar, CAT, bbar, p_pre + (size_t)2*BT*Hh, Hh, Ee);

    // sequential GRU scan (persistent)
    k_scan<<<128, 512>>>(Wr, Wz, Wbar);

    // LM head
    k_gemm<<<dim3(Vv / 64, BT / 64), 256>>>(p_hidden, Hh, Whead, Hh, bhead, out, Vv, Hh);
}

// round 3
// speedup vs baseline: 4.3042x; 4.3042x over previous
#include <cuda_runtime.h>
#include <math.h>
#include <stdint.h>

#define Bz   64
#define Tt   256
#define Vv   4096
#define Ee   512
#define Hh   1024
#define BT   (Bz*Tt)
#define CAT  (Ee+Hh)

__device__ float    g_emb[BT * Ee];
__device__ float    g_pre[3u * BT * Hh];      // [gate][bt][n]
__device__ float    g_hT[Hh * Bz];            // [n][m]
__device__ float    g_rhT[Hh * Bz];           // [n][m]
__device__ float    g_zzT[Hh * Bz];           // [n][m]
__device__ float    g_hidden[BT * Hh];        // [bt][n]
__device__ unsigned g_bar[1024];

__global__ void k_init(const float* __restrict__ start) {
    int i = blockIdx.x * blockDim.x + threadIdx.x;
    if (i < Hh * Bz) g_hT[i] = start[i >> 6];
    if (i < 1024)    g_bar[i] = 0u;
}

__global__ void k_embed(const int* __restrict__ x, const float* __restrict__ wte) {
    int i  = blockIdx.x * blockDim.x + threadIdx.x;
    int bt = i >> 7, e4 = i & 127;
    int tok = x[bt];
    reinterpret_cast<float4*>(g_emb)[i] =
        reinterpret_cast<const float4*>(wte + (size_t)tok * Ee)[e4];
}

// fp32 GEMM: C[M,N] = A[M,K] * W[N,K]^T + bias  (64x64 tile, 4x4/thread)
__global__ void __launch_bounds__(256) k_gemm(
    const float* __restrict__ A, int lda, const float* __restrict__ W, int ldw,
    const float* __restrict__ bias, float* __restrict__ C, int ldc, int K)
{
    __shared__ float As[32][64];
    __shared__ float Bs[32][64];
    const int tx = threadIdx.x & 15, ty = threadIdx.x >> 4;
    const int m0 = blockIdx.y * 64, n0 = blockIdx.x * 64;
    float acc[4][4] = {};
    for (int k0 = 0; k0 < K; k0 += 32) {
        #pragma unroll
        for (int r = 0; r < 2; r++) {
            int q = threadIdx.x + r * 256, row = q >> 3, kq = (q & 7) << 2;
            float4 av = *reinterpret_cast<const float4*>(A + (size_t)(m0 + row) * lda + k0 + kq);
            As[kq+0][row] = av.x; As[kq+1][row] = av.y; As[kq+2][row] = av.z; As[kq+3][row] = av.w;
            float4 bv = *reinterpret_cast<const float4*>(W + (size_t)(n0 + row) * ldw + k0 + kq);
            Bs[kq+0][row] = bv.x; Bs[kq+1][row] = bv.y; Bs[kq+2][row] = bv.z; Bs[kq+3][row] = bv.w;
        }
        __syncthreads();
        #pragma unroll
        for (int kk = 0; kk < 32; kk++) {
            float4 a = *reinterpret_cast<float4*>(&As[kk][ty*4]);
            float4 b = *reinterpret_cast<float4*>(&Bs[kk][tx*4]);
            float av[4] = {a.x,a.y,a.z,a.w}, bv[4] = {b.x,b.y,b.z,b.w};
            #pragma unroll
            for (int i = 0; i < 4; i++)
                #pragma unroll
                for (int j = 0; j < 4; j++) acc[i][j] = fmaf(av[i], bv[j], acc[i][j]);
        }
        __syncthreads();
    }
    #pragma unroll
    for (int i = 0; i < 4; i++) {
        int m = m0 + ty*4 + i, n = n0 + tx*4;
        float4 o;
        o.x = acc[i][0] + bias[n+0]; o.y = acc[i][1] + bias[n+1];
        o.z = acc[i][2] + bias[n+2]; o.w = acc[i][3] + bias[n+3];
        *reinterpret_cast<float4*>(C + (size_t)m * ldc + n) = o;
    }
}

__device__ __forceinline__ uint32_t smem_u32(const void* p) {
    uint32_t a;
    asm("{ .reg .u64 t; cvta.to.shared.u64 t, %1; cvt.u32.u64 %0, t; }" : "=r"(a) : "l"(p));
    return a;
}
#define CP_COMMIT() asm volatile("cp.async.commit_group;" ::: "memory")
#define CP_WAIT(n)  asm volatile("cp.async.wait_group %0;" :: "n"(n) : "memory")

__device__ __forceinline__ void gbarrier(int idx, unsigned G) {
    __syncthreads();
    if (threadIdx.x == 0) {
        __threadfence();
        unsigned a = atomicAdd(&g_bar[idx], 1u);
        if (a + 1u < G)
            while (*reinterpret_cast<volatile unsigned*>(&g_bar[idx]) < G) __nanosleep(32);
        __threadfence();
    }
    __syncthreads();
}

// persistent scan: 128 blocks x 512 threads, 160KB dynamic smem
// smem: ws1[1024][16] | ws2[1024][8] | hs[2][64][64] | red[8192]
__global__ void __launch_bounds__(512, 1) k_scan(
    const float* __restrict__ Wr, const float* __restrict__ Wz, const float* __restrict__ Wbar)
{
    extern __shared__ float smem[];
    float* ws1 = smem;
    float* ws2 = smem + 16384;
    float* hs  = smem + 24576;
    float* red = smem + 32768;

    const int tid = threadIdx.x;
    const int g   = blockIdx.x;
    const unsigned G = gridDim.x;
    const int n0p1 = (g & 63) * 16;
    const int n0p2 = g * 8;
    const bool isZ = (g >= 64);

    // load weights once (coalesced in global)
    const float* W1 = isZ ? Wz : Wr;
    for (int i = tid; i < 16384; i += 512) {
        int c = i >> 10, k = i & 1023;
        ws1[k*16 + c] = W1[(size_t)(n0p1 + c) * CAT + Ee + k];
    }
    for (int i = tid; i < 8192; i += 512) {
        int c = i >> 10, k = i & 1023;
        ws2[k*8 + c] = Wbar[(size_t)(n0p2 + c) * CAT + Ee + k];
    }
    __syncthreads();

    const int rg  = tid & 15, cg  = (tid >> 4) & 3, ks  = tid >> 6;   // phase1
    const int rg2 = tid & 15, cg2 = (tid >> 4) & 1, ks2 = tid >> 5;   // phase2
    const uint32_t hs_s = smem_u32(hs);
    const float* pre1 = g_pre + (isZ ? (size_t)BT * Hh : 0);
    const float* pre2 = g_pre + (size_t)2 * BT * Hh;

    for (int t = 0; t < Tt; t++) {
        // ---- prefetch pre-activations for this step ----
        int c1a = tid >> 6, m1 = tid & 63;                      // o = c*64+m
        float p1a = pre1[((size_t)(m1*Tt + t))*Hh + n0p1 + c1a];
        float p1b = pre1[((size_t)(m1*Tt + t))*Hh + n0p1 + c1a + 8];
        int c2 = tid >> 6 >= 8 ? 0 : tid >> 6;                  // only tid<512 all used
        float p2 = pre2[((size_t)(m1*Tt + t))*Hh + n0p2 + (tid >> 6 & 7)];

        // ================= phase 1: r / z =================
        float acc[4][4] = {};
        {
            // stage chunk 0
            {
                const float4* s = reinterpret_cast<const float4*>(g_hT);
                uint32_t d = hs_s;
                asm volatile("cp.async.ca.shared.global [%0], [%1], 16;" :: "r"(d + tid*16),       "l"(s + tid) : "memory");
                asm volatile("cp.async.ca.shared.global [%0], [%1], 16;" :: "r"(d + (tid+512)*16), "l"(s + tid + 512) : "memory");
            }
            CP_COMMIT();
            for (int kc = 0; kc < 16; kc++) {
                int buf = kc & 1;
                if (kc < 15) {
                    const float4* s = reinterpret_cast<const float4*>(g_hT + (kc+1)*4096);
                    uint32_t d = hs_s + ((kc+1)&1) * 16384;
                    asm volatile("cp.async.ca.shared.global [%0], [%1], 16;" :: "r"(d + tid*16),       "l"(s + tid) : "memory");
                    asm volatile("cp.async.ca.shared.global [%0], [%1], 16;" :: "r"(d + (tid+512)*16), "l"(s + tid + 512) : "memory");
                    CP_COMMIT();
                    CP_WAIT(1);
                } else {
                    CP_WAIT(0);
                }
                __syncthreads();
                const float* hb = hs + buf * 4096;
                #pragma unroll
                for (int j = 0; j < 8; j++) {
                    int kk = ks + 8*j;
                    float4 h4 = *reinterpret_cast<const float4*>(hb + kk*64 + rg*4);
                    float4 w4 = *reinterpret_cast<const float4*>(ws1 + (kc*64 + kk)*16 + cg*4);
                    float hv[4] = {h4.x,h4.y,h4.z,h4.w}, wv[4] = {w4.x,w4.y,w4.z,w4.w};
                    #pragma unroll
                    for (int i2 = 0; i2 < 4; i2++)
                        #pragma unroll
                        for (int j2 = 0; j2 < 4; j2++)
                            acc[i2][j2] = fmaf(hv[i2], wv[j2], acc[i2][j2]);
                }
                __syncthreads();
            }
            // reduce over 8 k-slices: red layout [ks][c][m]
            #pragma unroll
            for (int j2 = 0; j2 < 4; j2++)
                *reinterpret_cast<float4*>(red + ks*1024 + (cg*4 + j2)*64 + rg*4) =
                    make_float4(acc[0][j2], acc[1][j2], acc[2][j2], acc[3][j2]);
            __syncthreads();
            #pragma unroll
            for (int rep = 0; rep < 2; rep++) {
                int o = tid + rep*512;
                int c = o >> 6, m = o & 63, n = n0p1 + c;
                float s = (rep ? p1b : p1a);
                #pragma unroll
                for (int q = 0; q < 8; q++) s += red[q*1024 + c*64 + m];
                float sg = 1.f / (1.f + __expf(-s));
                if (!isZ) g_rhT[n*64 + m] = sg * g_hT[n*64 + m];
                else      g_zzT[n*64 + m] = sg;
            }
        }
        gbarrier(2*t, G);

        // ================= phase 2: hbar + update =================
        float acc2[4][4] = {};
        {
            {
                const float4* s = reinterpret_cast<const float4*>(g_rhT);
                uint32_t d = hs_s;
                asm volatile("cp.async.ca.shared.global [%0], [%1], 16;" :: "r"(d + tid*16),       "l"(s + tid) : "memory");
                asm volatile("cp.async.ca.shared.global [%0], [%1], 16;" :: "r"(d + (tid+512)*16), "l"(s + tid + 512) : "memory");
            }
            CP_COMMIT();
            for (int kc = 0; kc < 16; kc++) {
                int buf = kc & 1;
                if (kc < 15) {
                    const float4* s = reinterpret_cast<const float4*>(g_rhT + (kc+1)*4096);
                    uint32_t d = hs_s + ((kc+1)&1) * 16384;
                    asm volatile("cp.async.ca.shared.global [%0], [%1], 16;" :: "r"(d + tid*16),       "l"(s + tid) : "memory");
                    asm volatile("cp.async.ca.shared.global [%0], [%1], 16;" :: "r"(d + (tid+512)*16), "l"(s + tid + 512) : "memory");
                    CP_COMMIT();
                    CP_WAIT(1);
                } else {
                    CP_WAIT(0);
                }
                __syncthreads();
                const float* hb = hs + buf * 4096;
                #pragma unroll
                for (int j = 0; j < 4; j++) {
                    int kk = ks2 + 16*j;
                    float4 h4 = *reinterpret_cast<const float4*>(hb + kk*64 + rg2*4);
                    float4 w4 = *reinterpret_cast<const float4*>(ws2 + (kc*64 + kk)*8 + cg2*4);
                    float hv[4] = {h4.x,h4.y,h4.z,h4.w}, wv[4] = {w4.x,w4.y,w4.z,w4.w};
                    #pragma unroll
                    for (int i2 = 0; i2 < 4; i2++)
                        #pragma unroll
                        for (int j2 = 0; j2 < 4; j2++)
                            acc2[i2][j2] = fmaf(hv[i2], wv[j2], acc2[i2][j2]);
                }
                __syncthreads();
            }
            // red layout [ks2][c][m] : 16*8*64
            #pragma unroll
            for (int j2 = 0; j2 < 4; j2++)
                *reinterpret_cast<float4*>(red + ks2*512 + (cg2*4 + j2)*64 + rg2*4) =
                    make_float4(acc2[0][j2], acc2[1][j2], acc2[2][j2], acc2[3][j2]);
            __syncthreads();
            {
                int c = tid >> 6 & 7, m = tid & 63, n = n0p2 + c;
                float s = p2;
                #pragma unroll
                for (int q = 0; q < 16; q++) s += red[q*512 + c*64 + m];
                float hbar = tanhf(s);
                float z  = g_zzT[n*64 + m];
                float hp = g_hT[n*64 + m];
                float hn = fmaf(z, hbar - hp, hp);
                g_hT[n*64 + m] = hn;
                g_hidden[((size_t)(m*Tt + t))*Hh + n] = hn;
            }
        }
        gbarrier(2*t + 1, G);
    }
}

extern "C" void kernel_launch(void* const* d_in, const int* in_sizes, int n_in,
                              void* d_out, int out_size)
{
    const int*   x     = (const int*)  d_in[0];
    const float* start = (const float*)d_in[1];
    const float* wte   = (const float*)d_in[2];
    const float* Wr    = (const float*)d_in[3];
    const float* br    = (const float*)d_in[4];
    const float* Wbar  = (const float*)d_in[5];
    const float* bbar  = (const float*)d_in[6];
    const float* Wz    = (const float*)d_in[7];
    const float* bz    = (const float*)d_in[8];
    const float* Whead = (const float*)d_in[9];
    const float* bhead = (const float*)d_in[10];
    float* out = (float*)d_out;

    float *p_emb, *p_pre, *p_hidden;
    cudaGetSymbolAddress((void**)&p_emb,    g_emb);
    cudaGetSymbolAddress((void**)&p_pre,    g_pre);
    cudaGetSymbolAddress((void**)&p_hidden, g_hidden);

    static int smem_set = 0;
    if (!smem_set) {
        cudaFuncSetAttribute(k_scan, cudaFuncAttributeMaxDynamicSharedMemorySize, 163840);
        smem_set = 1;
    }

    k_init<<<256, 256>>>(start);
    k_embed<<<(BT * Ee / 4) / 256, 256>>>(x, wte);

    k_gemm<<<dim3(Hh/64, BT/64), 256>>>(p_emb, Ee, Wr,   CAT, br,   p_pre,                  Hh, Ee);
    k_gemm<<<dim3(Hh/64, BT/64), 256>>>(p_emb, Ee, Wz,   CAT, bz,   p_pre + (size_t)BT*Hh,  Hh, Ee);
    k_gemm<<<dim3(Hh/64, BT/64), 256>>>(p_emb, Ee, Wbar, CAT, bbar, p_pre + (size_t)2*BT*Hh, Hh, Ee);

    k_scan<<<128, 512, 163840>>>(Wr, Wz, Wbar);

    k_gemm<<<dim3(Vv/64, BT/64), 256>>>(p_hidden, Hh, Whead, Hh, bhead, out, Vv, Hh);
}

// round 5
// speedup vs baseline: 7.5720x; 1.7592x over previous
#include <cuda_runtime.h>
#include <cuda_bf16.h>
#include <math.h>
#include <stdint.h>

#define Bz   64
#define Tt   256
#define Vv   4096
#define Ee   512
#define Hh   1024
#define BT   (Bz*Tt)
#define CAT  (Ee+Hh)

// ---------------- static device scratch ----------------
__device__ float          g_pre[3u * BT * Hh];     // [gate][bt][n]
__device__ float          g_hT[Hh * Bz];
__device__ float          g_rhT[Hh * Bz];
__device__ float          g_zzT[Hh * Bz];
__device__ float          g_hidden[BT * Hh];       // [bt][n]
__device__ unsigned       g_bar[1024];
__device__ __nv_bfloat16  g_ehi[BT * Ee];
__device__ __nv_bfloat16  g_elo[BT * Ee];
__device__ __nv_bfloat16  g_hhi[BT * Hh];
__device__ __nv_bfloat16  g_hlo[BT * Hh];
__device__ __nv_bfloat16  g_wchi[3 * Hh * Ee];     // packed gate weights (E-part) [3072][512]
__device__ __nv_bfloat16  g_wclo[3 * Hh * Ee];
__device__ __nv_bfloat16  g_whhi[Vv * Hh];
__device__ __nv_bfloat16  g_whlo[Vv * Hh];

// ---------------- helpers ----------------
__device__ __forceinline__ uint32_t smem_u32(const void* p) {
    uint32_t a;
    asm("{ .reg .u64 t; cvta.to.shared.u64 t, %1; cvt.u32.u64 %0, t; }" : "=r"(a) : "l"(p));
    return a;
}
#define CP_COMMIT() asm volatile("cp.async.commit_group;" ::: "memory")
#define CP_WAIT(n)  asm volatile("cp.async.wait_group %0;" :: "n"(n) : "memory")
#define SW128(x) ((x) ^ (((x) >> 3) & 0x70))

#define LDSM4(r, addr) \
    asm volatile("ldmatrix.sync.aligned.m8n8.x4.shared.b16 {%0,%1,%2,%3}, [%4];" \
        : "=r"((r)[0]), "=r"((r)[1]), "=r"((r)[2]), "=r"((r)[3]) : "r"(addr))

#define MMA(d, a, b) \
    asm volatile("mma.sync.aligned.m16n8k16.row.col.f32.bf16.bf16.f32 " \
        "{%0,%1,%2,%3}, {%4,%5,%6,%7}, {%8,%9}, {%0,%1,%2,%3};" \
        : "+f"((d)[0]), "+f"((d)[1]), "+f"((d)[2]), "+f"((d)[3]) \
        : "r"((a)[0]), "r"((a)[1]), "r"((a)[2]), "r"((a)[3]), "r"((b)[0]), "r"((b)[1]))

// ---------------- init / embed / converters ----------------
__global__ void k_init(const float* __restrict__ start) {
    int i = blockIdx.x * blockDim.x + threadIdx.x;
    if (i < Hh * Bz) g_hT[i] = start[i >> 6];
    if (i < 1024)    g_bar[i] = 0u;
}
__device__ __forceinline__ void split2(float a, float b, __nv_bfloat162* hi, __nv_bfloat162* lo) {
    __nv_bfloat16 ah = __float2bfloat16(a), bh = __float2bfloat16(b);
    *hi = __nv_bfloat162(ah, bh);
    *lo = __nv_bfloat162(__float2bfloat16(a - __bfloat162float(ah)),
                         __float2bfloat16(b - __bfloat162float(bh)));
}
__global__ void k_embed(const int* __restrict__ x, const float* __restrict__ wte) {
    int i  = blockIdx.x * blockDim.x + threadIdx.x;   // 4 floats per thread
    int bt = i >> 7, e4 = i & 127;
    int tok = x[bt];
    float4 v = reinterpret_cast<const float4*>(wte + (size_t)tok * Ee)[e4];
    __nv_bfloat162 h0, l0, h1, l1;
    split2(v.x, v.y, &h0, &l0); split2(v.z, v.w, &h1, &l1);
    reinterpret_cast<__nv_bfloat162*>(g_ehi)[2*i]   = h0;
    reinterpret_cast<__nv_bfloat162*>(g_ehi)[2*i+1] = h1;
    reinterpret_cast<__nv_bfloat162*>(g_elo)[2*i]   = l0;
    reinterpret_cast<__nv_bfloat162*>(g_elo)[2*i+1] = l1;
}
__global__ void k_cvt(const float* __restrict__ src, __nv_bfloat16* __restrict__ hi,
                      __nv_bfloat16* __restrict__ lo) {
    int i = blockIdx.x * blockDim.x + threadIdx.x;    // 4 floats per thread
    float4 v = reinterpret_cast<const float4*>(src)[i];
    __nv_bfloat162 h0, l0, h1, l1;
    split2(v.x, v.y, &h0, &l0); split2(v.z, v.w, &h1, &l1);
    reinterpret_cast<__nv_bfloat162*>(hi)[2*i]   = h0;
    reinterpret_cast<__nv_bfloat162*>(hi)[2*i+1] = h1;
    reinterpret_cast<__nv_bfloat162*>(lo)[2*i]   = l0;
    reinterpret_cast<__nv_bfloat162*>(lo)[2*i+1] = l1;
}
__global__ void k_cvt_wcat(const float* __restrict__ Wr, const float* __restrict__ Wz,
                           const float* __restrict__ Wbar) {
    int i = blockIdx.x * blockDim.x + threadIdx.x;    // 3072*512 scalars
    int row = i >> 9, col = i & 511;
    const float* W = (row < 1024) ? Wr : (row < 2048) ? Wz : Wbar;
    float v = W[(size_t)(row & 1023) * CAT + col];
    __nv_bfloat16 h = __float2bfloat16(v);
    g_wchi[i] = h;
    g_wclo[i] = __float2bfloat16(v - __bfloat162float(h));
}

// ---------------- split-bf16 HMMA GEMM ----------------
// C[M,N] = (Ahi+Alo)[M,K]*(Bhi+Blo)[N,K]^T + bias
// CTA 128x128, 8 warps (4m x 2n), warp 32x64, K-chunk 64, 2-stage cp.async
#define STG      65536
#define SOFF_ALO 16384
#define SOFF_BHI 32768
#define SOFF_BLO 49152
#define SM_TOTAL 131072

__device__ __forceinline__ void load_chunk(
    uint32_t sb, int s, int tid,
    const __nv_bfloat16* Ahi, const __nv_bfloat16* Alo,
    const __nv_bfloat16* Bhi, const __nv_bfloat16* Blo,
    int m0, int n0, int kc, int K)
{
    uint32_t st = sb + s * STG;
    int kb = kc * 64;
    #pragma unroll
    for (int j = 0; j < 4; j++) {
        int q = tid + j * 256, row = q >> 3, kg = q & 7;
        uint32_t d = SW128((uint32_t)(row * 128 + kg * 16));
        size_t srcA = (size_t)(m0 + row) * K + kb + kg * 8;
        size_t srcB = (size_t)(n0 + row) * K + kb + kg * 8;
        asm volatile("cp.async.cg.shared.global [%0], [%1], 16;" :: "r"(st + d),            "l"(Ahi + srcA) : "memory");
        asm volatile("cp.async.cg.shared.global [%0], [%1], 16;" :: "r"(st + SOFF_ALO + d), "l"(Alo + srcA) : "memory");
        asm volatile("cp.async.cg.shared.global [%0], [%1], 16;" :: "r"(st + SOFF_BHI + d), "l"(Bhi + srcB) : "memory");
        asm volatile("cp.async.cg.shared.global [%0], [%1], 16;" :: "r"(st + SOFF_BLO + d), "l"(Blo + srcB) : "memory");
    }
}

__global__ void __launch_bounds__(256, 1) k_tgemm(
    const __nv_bfloat16* __restrict__ Ahi, const __nv_bfloat16* __restrict__ Alo,
    const __nv_bfloat16* __restrict__ Bhi, const __nv_bfloat16* __restrict__ Blo,
    const float* __restrict__ bias, float* __restrict__ C, int K, int ldc, int nk)
{
    extern __shared__ char smem[];
    const uint32_t sb = smem_u32(smem);
    const int tid = threadIdx.x, lane = tid & 31, wid = tid >> 5;
    const int wm = wid & 3, wn = wid >> 2;
    const int m0 = blockIdx.y * 128, n0 = blockIdx.x * 128;

    float acc[2][8][4] = {};

    load_chunk(sb, 0, tid, Ahi, Alo, Bhi, Blo, m0, n0, 0, K);
    CP_COMMIT();

    for (int kc = 0; kc < nk; kc++) {
        if (kc + 1 < nk) {
            load_chunk(sb, (kc + 1) & 1, tid, Ahi, Alo, Bhi, Blo, m0, n0, kc + 1, K);
            CP_COMMIT();
            CP_WAIT(1);
        } else {
            CP_WAIT(0);
        }
        __syncthreads();

        const uint32_t st = sb + (kc & 1) * STG;
        #pragma unroll
        for (int ks = 0; ks < 4; ks++) {
            // A fragments (2 m16 tiles, hi+lo)
            uint32_t a_hi[2][4], a_lo[2][4];
            {
                int acol = ks * 32 + (lane >> 4) * 16;
                #pragma unroll
                for (int mt = 0; mt < 2; mt++) {
                    int arow = wm * 32 + mt * 16 + (lane & 15);
                    uint32_t off = SW128((uint32_t)(arow * 128 + acol));
                    LDSM4(a_hi[mt], st + off);
                    LDSM4(a_lo[mt], st + SOFF_ALO + off);
                }
            }
            // B fragments (8 n8 tiles, hi+lo) — x4 loads 2 tiles each
            uint32_t b_hi[8][2], b_lo[8][2];
            {
                int bcol  = ks * 32 + ((lane >> 3) & 1) * 16;
                int brofs = (lane >> 4) * 8 + (lane & 7);
                #pragma unroll
                for (int nt2 = 0; nt2 < 4; nt2++) {
                    int brow = wn * 64 + nt2 * 16 + brofs;
                    uint32_t off = SW128((uint32_t)(brow * 128 + bcol));
                    uint32_t r[4];
                    LDSM4(r, st + SOFF_BHI + off);
                    b_hi[nt2*2][0]   = r[0]; b_hi[nt2*2][1]   = r[1];
                    b_hi[nt2*2+1][0] = r[2]; b_hi[nt2*2+1][1] = r[3];
                    LDSM4(r, st + SOFF_BLO + off);
                    b_lo[nt2*2][0]   = r[0]; b_lo[nt2*2][1]   = r[1];
                    b_lo[nt2*2+1][0] = r[2]; b_lo[nt2*2+1][1] = r[3];
                }
            }
            #pragma unroll
            for (int mt = 0; mt < 2; mt++)
                #pragma unroll
                for (int nt = 0; nt < 8; nt++) {
                    MMA(acc[mt][nt], a_hi[mt], b_hi[nt]);
                    MMA(acc[mt][nt], a_hi[mt], b_lo[nt]);
                    MMA(acc[mt][nt], a_lo[mt], b_hi[nt]);
                }
        }
        __syncthreads();
    }

    // epilogue
    const int g = lane >> 2, tg = lane & 3;
    #pragma unroll
    for (int nt = 0; nt < 8; nt++) {
        int col = n0 + wn * 64 + nt * 8 + tg * 2;
        float b0 = bias[col], b1 = bias[col + 1];
        #pragma unroll
        for (int mt = 0; mt < 2; mt++) {
            int r0 = m0 + wm * 32 + mt * 16 + g;
            float2 v0 = make_float2(acc[mt][nt][0] + b0, acc[mt][nt][1] + b1);
            float2 v1 = make_float2(acc[mt][nt][2] + b0, acc[mt][nt][3] + b1);
            *reinterpret_cast<float2*>(C + (size_t)r0 * ldc + col)       = v0;
            *reinterpret_cast<float2*>(C + (size_t)(r0 + 8) * ldc + col) = v1;
        }
    }
}

// ---------------- grid barrier ----------------
__device__ __forceinline__ void gbarrier(int idx, unsigned G) {
    __syncthreads();
    if (threadIdx.x == 0) {
        __threadfence();
        unsigned a = atomicAdd(&g_bar[idx], 1u);
        if (a + 1u < G)
            while (*reinterpret_cast<volatile unsigned*>(&g_bar[idx]) < G) __nanosleep(32);
        __threadfence();
    }
    __syncthreads();
}

// ---------------- persistent GRU scan (unchanged from R3) ----------------
__global__ void __launch_bounds__(512, 1) k_scan(
    const float* __restrict__ Wr, const float* __restrict__ Wz, const float* __restrict__ Wbar)
{
    extern __shared__ float smemf[];
    float* ws1 = smemf;
    float* ws2 = smemf + 16384;
    float* hs  = smemf + 24576;
    float* red = smemf + 32768;

    const int tid = threadIdx.x;
    const int g   = blockIdx.x;
    const unsigned G = gridDim.x;
    const int n0p1 = (g & 63) * 16;
    const int n0p2 = g * 8;
    const bool isZ = (g >= 64);

    const float* W1 = isZ ? Wz : Wr;
    for (int i = tid; i < 16384; i += 512) {
        int c = i >> 10, k = i & 1023;
        ws1[k*16 + c] = W1[(size_t)(n0p1 + c) * CAT + Ee + k];
    }
    for (int i = tid; i < 8192; i += 512) {
        int c = i >> 10, k = i & 1023;
        ws2[k*8 + c] = Wbar[(size_t)(n0p2 + c) * CAT + Ee + k];
    }
    __syncthreads();

    const int rg  = tid & 15, cg  = (tid >> 4) & 3, ks  = tid >> 6;
    const int rg2 = tid & 15, cg2 = (tid >> 4) & 1, ks2 = tid >> 5;
    const uint32_t hs_s = smem_u32(hs);
    const float* pre1 = g_pre + (isZ ? (size_t)BT * Hh : 0);
    const float* pre2 = g_pre + (size_t)2 * BT * Hh;

    for (int t = 0; t < Tt; t++) {
        int c1a = tid >> 6, m1 = tid & 63;
        float p1a = pre1[((size_t)(m1*Tt + t))*Hh + n0p1 + c1a];
        float p1b = pre1[((size_t)(m1*Tt + t))*Hh + n0p1 + c1a + 8];
        float p2  = pre2[((size_t)(m1*Tt + t))*Hh + n0p2 + (tid >> 6 & 7)];

        float acc[4][4] = {};
        {
            {
                const float4* s = reinterpret_cast<const float4*>(g_hT);
                uint32_t d = hs_s;
                asm volatile("cp.async.ca.shared.global [%0], [%1], 16;" :: "r"(d + tid*16),       "l"(s + tid) : "memory");
                asm volatile("cp.async.ca.shared.global [%0], [%1], 16;" :: "r"(d + (tid+512)*16), "l"(s + tid + 512) : "memory");
            }
            CP_COMMIT();
            for (int kc = 0; kc < 16; kc++) {
                int buf = kc & 1;
                if (kc < 15) {
                    const float4* s = reinterpret_cast<const float4*>(g_hT + (kc+1)*4096);
                    uint32_t d = hs_s + ((kc+1)&1) * 16384;
                    asm volatile("cp.async.ca.shared.global [%0], [%1], 16;" :: "r"(d + tid*16),       "l"(s + tid) : "memory");
                    asm volatile("cp.async.ca.shared.global [%0], [%1], 16;" :: "r"(d + (tid+512)*16), "l"(s + tid + 512) : "memory");
                    CP_COMMIT();
                    CP_WAIT(1);
                } else { CP_WAIT(0); }
                __syncthreads();
                const float* hb = hs + buf * 4096;
                #pragma unroll
                for (int j = 0; j < 8; j++) {
                    int kk = ks + 8*j;
                    float4 h4 = *reinterpret_cast<const float4*>(hb + kk*64 + rg*4);
                    float4 w4 = *reinterpret_cast<const float4*>(ws1 + (kc*64 + kk)*16 + cg*4);
                    float hv[4] = {h4.x,h4.y,h4.z,h4.w}, wv[4] = {w4.x,w4.y,w4.z,w4.w};
                    #pragma unroll
                    for (int i2 = 0; i2 < 4; i2++)
                        #pragma unroll
                        for (int j2 = 0; j2 < 4; j2++)
                            acc[i2][j2] = fmaf(hv[i2], wv[j2], acc[i2][j2]);
                }
                __syncthreads();
            }
            #pragma unroll
            for (int j2 = 0; j2 < 4; j2++)
                *reinterpret_cast<float4*>(red + ks*1024 + (cg*4 + j2)*64 + rg*4) =
                    make_float4(acc[0][j2], acc[1][j2], acc[2][j2], acc[3][j2]);
            __syncthreads();
            #pragma unroll
            for (int rep = 0; rep < 2; rep++) {
                int o = tid + rep*512;
                int c = o >> 6, m = o & 63, n = n0p1 + c;
                float s = (rep ? p1b : p1a);
                #pragma unroll
                for (int q = 0; q < 8; q++) s += red[q*1024 + c*64 + m];
                float sg = 1.f / (1.f + __expf(-s));
                if (!isZ) g_rhT[n*64 + m] = sg * g_hT[n*64 + m];
                else      g_zzT[n*64 + m] = sg;
            }
        }
        gbarrier(2*t, G);

        float acc2[4][4] = {};
        {
            {
                const float4* s = reinterpret_cast<const float4*>(g_rhT);
                uint32_t d = hs_s;
                asm volatile("cp.async.ca.shared.global [%0], [%1], 16;" :: "r"(d + tid*16),       "l"(s + tid) : "memory");
                asm volatile("cp.async.ca.shared.global [%0], [%1], 16;" :: "r"(d + (tid+512)*16), "l"(s + tid + 512) : "memory");
            }
            CP_COMMIT();
            for (int kc = 0; kc < 16; kc++) {
                int buf = kc & 1;
                if (kc < 15) {
                    const float4* s = reinterpret_cast<const float4*>(g_rhT + (kc+1)*4096);
                    uint32_t d = hs_s + ((kc+1)&1) * 16384;
                    asm volatile("cp.async.ca.shared.global [%0], [%1], 16;" :: "r"(d + tid*16),       "l"(s + tid) : "memory");
                    asm volatile("cp.async.ca.shared.global [%0], [%1], 16;" :: "r"(d + (tid+512)*16), "l"(s + tid + 512) : "memory");
                    CP_COMMIT();
                    CP_WAIT(1);
                } else { CP_WAIT(0); }
                __syncthreads();
                const float* hb = hs + buf * 4096;
                #pragma unroll
                for (int j = 0; j < 4; j++) {
                    int kk = ks2 + 16*j;
                    float4 h4 = *reinterpret_cast<const float4*>(hb + kk*64 + rg2*4);
                    float4 w4 = *reinterpret_cast<const float4*>(ws2 + (kc*64 + kk)*8 + cg2*4);
                    float hv[4] = {h4.x,h4.y,h4.z,h4.w}, wv[4] = {w4.x,w4.y,w4.z,w4.w};
                    #pragma unroll
                    for (int i2 = 0; i2 < 4; i2++)
                        #pragma unroll
                        for (int j2 = 0; j2 < 4; j2++)
                            acc2[i2][j2] = fmaf(hv[i2], wv[j2], acc2[i2][j2]);
                }
                __syncthreads();
            }
            #pragma unroll
            for (int j2 = 0; j2 < 4; j2++)
                *reinterpret_cast<float4*>(red + ks2*512 + (cg2*4 + j2)*64 + rg2*4) =
                    make_float4(acc2[0][j2], acc2[1][j2], acc2[2][j2], acc2[3][j2]);
            __syncthreads();
            {
                int c = tid >> 6 & 7, m = tid & 63, n = n0p2 + c;
                float s = p2;
                #pragma unroll
                for (int q = 0; q < 16; q++) s += red[q*512 + c*64 + m];
                float hbar = tanhf(s);
                float z  = g_zzT[n*64 + m];
                float hp = g_hT[n*64 + m];
                float hn = fmaf(z, hbar - hp, hp);
                g_hT[n*64 + m] = hn;
                g_hidden[((size_t)(m*Tt + t))*Hh + n] = hn;
            }
        }
        gbarrier(2*t + 1, G);
    }
}

// ---------------- launch ----------------
extern "C" void kernel_launch(void* const* d_in, const int* in_sizes, int n_in,
                              void* d_out, int out_size)
{
    const int*   x     = (const int*)  d_in[0];
    const float* start = (const float*)d_in[1];
    const float* wte   = (const float*)d_in[2];
    const float* Wr    = (const float*)d_in[3];
    const float* br    = (const float*)d_in[4];
    const float* Wbar  = (const float*)d_in[5];
    const float* bbar  = (const float*)d_in[6];
    const float* Wz    = (const float*)d_in[7];
    const float* bz    = (const float*)d_in[8];
    const float* Whead = (const float*)d_in[9];
    const float* bhead = (const float*)d_in[10];
    float* out = (float*)d_out;

    float *p_pre, *p_hidden;
    __nv_bfloat16 *p_ehi, *p_elo, *p_hhi, *p_hlo, *p_wchi, *p_wclo, *p_whhi, *p_whlo;
    cudaGetSymbolAddress((void**)&p_pre,    g_pre);
    cudaGetSymbolAddress((void**)&p_hidden, g_hidden);
    cudaGetSymbolAddress((void**)&p_ehi,  g_ehi);   cudaGetSymbolAddress((void**)&p_elo,  g_elo);
    cudaGetSymbolAddress((void**)&p_hhi,  g_hhi);   cudaGetSymbolAddress((void**)&p_hlo,  g_hlo);
    cudaGetSymbolAddress((void**)&p_wchi, g_wchi);  cudaGetSymbolAddress((void**)&p_wclo, g_wclo);
    cudaGetSymbolAddress((void**)&p_whhi, g_whhi);  cudaGetSymbolAddress((void**)&p_whlo, g_whlo);

    cudaFuncSetAttribute(k_scan,  cudaFuncAttributeMaxDynamicSharedMemorySize, 163840);
    cudaFuncSetAttribute(k_tgemm, cudaFuncAttributeMaxDynamicSharedMemorySize, SM_TOTAL);

    k_init<<<256, 256>>>(start);
    k_embed<<<(BT * Ee / 4) / 256, 256>>>(x, wte);
    k_cvt_wcat<<<(3 * Hh * Ee) / 256, 256>>>(Wr, Wz, Wbar);
    k_cvt<<<(Vv * Hh / 4) / 256, 256>>>(Whead, p_whhi, p_whlo);

    // pre-projections: 3 gates, N=1024 each, K=512
    for (int gate = 0; gate < 3; gate++) {
        const float* bias = (gate == 0) ? br : (gate == 1) ? bz : bbar;
        k_tgemm<<<dim3(Hh/128, BT/128), 256, SM_TOTAL>>>(
            p_ehi, p_elo,
            p_wchi + (size_t)gate * Hh * Ee, p_wclo + (size_t)gate * Hh * Ee,
            bias, p_pre + (size_t)gate * BT * Hh, Ee, Hh, Ee/64);
    }

    k_scan<<<128, 512, 163840>>>(Wr, Wz, Wbar);

    k_cvt<<<(BT * Hh / 4) / 256, 256>>>(p_hidden, p_hhi, p_hlo);
    k_tgemm<<<dim3(Vv/128, BT/128), 256, SM_TOTAL>>>(
        p_hhi, p_hlo, p_whhi, p_whlo, bhead, out, Hh, Vv, Hh/64);
}

// round 6
// speedup vs baseline: 10.6476x; 1.4062x over previous
#include <cuda_runtime.h>
#include <cuda_bf16.h>
#include <math.h>
#include <stdint.h>

#define Bz   64
#define Tt   256
#define Vv   4096
#define Ee   512
#define Hh   1024
#define BT   (Bz*Tt)
#define CAT  (Ee+Hh)

// ---------------- static device scratch ----------------
__device__ float          g_pre[3u * BT * Hh];     // [gate][bt][n] gate 0=r,1=z,2=hbar
__device__ float          g_h[Bz * Hh];            // fp32 state [m][n]
__device__ float          g_zz[Bz * Hh];           // z [m][n]
__device__ __nv_bfloat16  g_shhi[Bz * Hh];         // state hi/lo [m][k]
__device__ __nv_bfloat16  g_shlo[Bz * Hh];
__device__ __nv_bfloat16  g_rhhi[Bz * Hh];         // r*h hi/lo [m][k]
__device__ __nv_bfloat16  g_rhlo[Bz * Hh];
__device__ unsigned       g_bar[1024];
__device__ __nv_bfloat16  g_ehi[BT * Ee];
__device__ __nv_bfloat16  g_elo[BT * Ee];
__device__ __nv_bfloat16  g_hhi[BT * Hh];          // hidden (head input) [bt][k]
__device__ __nv_bfloat16  g_hlo[BT * Hh];
__device__ __nv_bfloat16  g_wchi[3 * Hh * Ee];     // gate weights E-part [3072][512]
__device__ __nv_bfloat16  g_wclo[3 * Hh * Ee];
__device__ __nv_bfloat16  g_wHhi[3u * Hh * Hh];    // gate weights H-part [3][1024][1024]
__device__ __nv_bfloat16  g_wHlo[3u * Hh * Hh];
__device__ __nv_bfloat16  g_whhi[Vv * Hh];
__device__ __nv_bfloat16  g_whlo[Vv * Hh];

// ---------------- helpers ----------------
__device__ __forceinline__ uint32_t smem_u32(const void* p) {
    uint32_t a;
    asm("{ .reg .u64 t; cvta.to.shared.u64 t, %1; cvt.u32.u64 %0, t; }" : "=r"(a) : "l"(p));
    return a;
}
#define CP_COMMIT() asm volatile("cp.async.commit_group;" ::: "memory")
#define CP_WAIT(n)  asm volatile("cp.async.wait_group %0;" :: "n"(n) : "memory")
#define CPA(dst, src) \
    asm volatile("cp.async.cg.shared.global [%0], [%1], 16;" :: "r"(dst), "l"(src) : "memory")
#define SW128(x) ((x) ^ (((x) >> 3) & 0x70))

#define LDSM4(r, addr) \
    asm volatile("ldmatrix.sync.aligned.m8n8.x4.shared.b16 {%0,%1,%2,%3}, [%4];" \
        : "=r"((r)[0]), "=r"((r)[1]), "=r"((r)[2]), "=r"((r)[3]) : "r"(addr))

#define MMA(d, a, b) \
    asm volatile("mma.sync.aligned.m16n8k16.row.col.f32.bf16.bf16.f32 " \
        "{%0,%1,%2,%3}, {%4,%5,%6,%7}, {%8,%9}, {%0,%1,%2,%3};" \
        : "+f"((d)[0]), "+f"((d)[1]), "+f"((d)[2]), "+f"((d)[3]) \
        : "r"((a)[0]), "r"((a)[1]), "r"((a)[2]), "r"((a)[3]), "r"((b)[0]), "r"((b)[1]))

__device__ __forceinline__ void split2(float a, float b, __nv_bfloat162* hi, __nv_bfloat162* lo) {
    __nv_bfloat16 ah = __float2bfloat16(a), bh = __float2bfloat16(b);
    *hi = __nv_bfloat162(ah, bh);
    *lo = __nv_bfloat162(__float2bfloat16(a - __bfloat162float(ah)),
                         __float2bfloat16(b - __bfloat162float(bh)));
}

// ---------------- init / embed / converters ----------------
__global__ void k_init(const float* __restrict__ start) {
    int i = blockIdx.x * blockDim.x + threadIdx.x;   // 65536
    float v = start[i & 1023];
    g_h[i] = v;
    __nv_bfloat16 h = __float2bfloat16(v);
    g_shhi[i] = h;
    g_shlo[i] = __float2bfloat16(v - __bfloat162float(h));
    if (i < 1024) g_bar[i] = 0u;
}
__global__ void k_embed(const int* __restrict__ x, const float* __restrict__ wte) {
    int i  = blockIdx.x * blockDim.x + threadIdx.x;
    int bt = i >> 7, e4 = i & 127;
    int tok = x[bt];
    float4 v = reinterpret_cast<const float4*>(wte + (size_t)tok * Ee)[e4];
    __nv_bfloat162 h0, l0, h1, l1;
    split2(v.x, v.y, &h0, &l0); split2(v.z, v.w, &h1, &l1);
    reinterpret_cast<__nv_bfloat162*>(g_ehi)[2*i]   = h0;
    reinterpret_cast<__nv_bfloat162*>(g_ehi)[2*i+1] = h1;
    reinterpret_cast<__nv_bfloat162*>(g_elo)[2*i]   = l0;
    reinterpret_cast<__nv_bfloat162*>(g_elo)[2*i+1] = l1;
}
__global__ void k_cvt(const float* __restrict__ src, __nv_bfloat16* __restrict__ hi,
                      __nv_bfloat16* __restrict__ lo) {
    int i = blockIdx.x * blockDim.x + threadIdx.x;
    float4 v = reinterpret_cast<const float4*>(src)[i];
    __nv_bfloat162 h0, l0, h1, l1;
    split2(v.x, v.y, &h0, &l0); split2(v.z, v.w, &h1, &l1);
    reinterpret_cast<__nv_bfloat162*>(hi)[2*i]   = h0;
    reinterpret_cast<__nv_bfloat162*>(hi)[2*i+1] = h1;
    reinterpret_cast<__nv_bfloat162*>(lo)[2*i]   = l0;
    reinterpret_cast<__nv_bfloat162*>(lo)[2*i+1] = l1;
}
__global__ void k_cvt_wcat(const float* __restrict__ Wr, const float* __restrict__ Wz,
                           const float* __restrict__ Wbar) {
    int i = blockIdx.x * blockDim.x + threadIdx.x;    // 3072*512
    int row = i >> 9, col = i & 511;
    const float* W = (row < 1024) ? Wr : (row < 2048) ? Wz : Wbar;
    float v = W[(size_t)(row & 1023) * CAT + col];
    __nv_bfloat16 h = __float2bfloat16(v);
    g_wchi[i] = h;
    g_wclo[i] = __float2bfloat16(v - __bfloat162float(h));
}
__global__ void k_cvt_wH(const float* __restrict__ Wr, const float* __restrict__ Wz,
                         const float* __restrict__ Wbar) {
    int i = blockIdx.x * blockDim.x + threadIdx.x;    // 3*1024*1024
    int gate = i >> 20, row = (i >> 10) & 1023, col = i & 1023;
    const float* W = (gate == 0) ? Wr : (gate == 1) ? Wz : Wbar;
    float v = W[(size_t)row * CAT + Ee + col];
    __nv_bfloat16 h = __float2bfloat16(v);
    g_wHhi[i] = h;
    g_wHlo[i] = __float2bfloat16(v - __bfloat162float(h));
}

// ---------------- split-bf16 HMMA GEMM (pre-projections + head) ----------------
#define STG      65536
#define SOFF_ALO 16384
#define SOFF_BHI 32768
#define SOFF_BLO 49152
#define SM_TOTAL 131072

__device__ __forceinline__ void load_chunk(
    uint32_t sb, int s, int tid,
    const __nv_bfloat16* Ahi, const __nv_bfloat16* Alo,
    const __nv_bfloat16* Bhi, const __nv_bfloat16* Blo,
    int m0, int n0, int kc, int K)
{
    uint32_t st = sb + s * STG;
    int kb = kc * 64;
    #pragma unroll
    for (int j = 0; j < 4; j++) {
        int q = tid + j * 256, row = q >> 3, kg = q & 7;
        uint32_t d = SW128((uint32_t)(row * 128 + kg * 16));
        size_t srcA = (size_t)(m0 + row) * K + kb + kg * 8;
        size_t srcB = (size_t)(n0 + row) * K + kb + kg * 8;
        CPA(st + d,            Ahi + srcA);
        CPA(st + SOFF_ALO + d, Alo + srcA);
        CPA(st + SOFF_BHI + d, Bhi + srcB);
        CPA(st + SOFF_BLO + d, Blo + srcB);
    }
}

__global__ void __launch_bounds__(256, 1) k_tgemm(
    const __nv_bfloat16* __restrict__ Ahi, const __nv_bfloat16* __restrict__ Alo,
    const __nv_bfloat16* __restrict__ Bhi, const __nv_bfloat16* __restrict__ Blo,
    const float* __restrict__ bias, float* __restrict__ C, int K, int ldc, int nk)
{
    extern __shared__ char smem[];
    const uint32_t sb = smem_u32(smem);
    const int tid = threadIdx.x, lane = tid & 31, wid = tid >> 5;
    const int wm = wid & 3, wn = wid >> 2;
    const int m0 = blockIdx.y * 128, n0 = blockIdx.x * 128;

    float acc[2][8][4] = {};

    load_chunk(sb, 0, tid, Ahi, Alo, Bhi, Blo, m0, n0, 0, K);
    CP_COMMIT();

    for (int kc = 0; kc < nk; kc++) {
        if (kc + 1 < nk) {
            load_chunk(sb, (kc + 1) & 1, tid, Ahi, Alo, Bhi, Blo, m0, n0, kc + 1, K);
            CP_COMMIT();
            CP_WAIT(1);
        } else {
            CP_WAIT(0);
        }
        __syncthreads();

        const uint32_t st = sb + (kc & 1) * STG;
        #pragma unroll
        for (int ks = 0; ks < 4; ks++) {
            uint32_t a_hi[2][4], a_lo[2][4];
            {
                int acol = ks * 32 + (lane >> 4) * 16;
                #pragma unroll
                for (int mt = 0; mt < 2; mt++) {
                    int arow = wm * 32 + mt * 16 + (lane & 15);
                    uint32_t off = SW128((uint32_t)(arow * 128 + acol));
                    LDSM4(a_hi[mt], st + off);
                    LDSM4(a_lo[mt], st + SOFF_ALO + off);
                }
            }
            uint32_t b_hi[8][2], b_lo[8][2];
            {
                int bcol  = ks * 32 + ((lane >> 3) & 1) * 16;
                int brofs = (lane >> 4) * 8 + (lane & 7);
                #pragma unroll
                for (int nt2 = 0; nt2 < 4; nt2++) {
                    int brow = wn * 64 + nt2 * 16 + brofs;
                    uint32_t off = SW128((uint32_t)(brow * 128 + bcol));
                    uint32_t r[4];
                    LDSM4(r, st + SOFF_BHI + off);
                    b_hi[nt2*2][0]   = r[0]; b_hi[nt2*2][1]   = r[1];
                    b_hi[nt2*2+1][0] = r[2]; b_hi[nt2*2+1][1] = r[3];
                    LDSM4(r, st + SOFF_BLO + off);
                    b_lo[nt2*2][0]   = r[0]; b_lo[nt2*2][1]   = r[1];
                    b_lo[nt2*2+1][0] = r[2]; b_lo[nt2*2+1][1] = r[3];
                }
            }
            #pragma unroll
            for (int mt = 0; mt < 2; mt++)
                #pragma unroll
                for (int nt = 0; nt < 8; nt++) {
                    MMA(acc[mt][nt], a_hi[mt], b_hi[nt]);
                    MMA(acc[mt][nt], a_hi[mt], b_lo[nt]);
                    MMA(acc[mt][nt], a_lo[mt], b_hi[nt]);
                }
        }
        __syncthreads();
    }

    const int g = lane >> 2, tg = lane & 3;
    #pragma unroll
    for (int nt = 0; nt < 8; nt++) {
        int col = n0 + wn * 64 + nt * 8 + tg * 2;
        float b0 = bias[col], b1 = bias[col + 1];
        #pragma unroll
        for (int mt = 0; mt < 2; mt++) {
            int r0 = m0 + wm * 32 + mt * 16 + g;
            float2 v0 = make_float2(acc[mt][nt][0] + b0, acc[mt][nt][1] + b1);
            float2 v1 = make_float2(acc[mt][nt][2] + b0, acc[mt][nt][3] + b1);
            *reinterpret_cast<float2*>(C + (size_t)r0 * ldc + col)       = v0;
            *reinterpret_cast<float2*>(C + (size_t)(r0 + 8) * ldc + col) = v1;
        }
    }
}

// ---------------- grid barrier ----------------
__device__ __forceinline__ void gbarrier(int idx, unsigned G) {
    __syncthreads();
    if (threadIdx.x == 0) {
        __threadfence();
        unsigned a = atomicAdd(&g_bar[idx], 1u);
        if (a + 1u < G)
            while (*reinterpret_cast<volatile unsigned*>(&g_bar[idx]) < G) __nanosleep(32);
        __threadfence();
    }
    __syncthreads();
}

// ---------------- HMMA persistent scan ----------------
// 128 blocks x 256 threads. smem: WS1 64K | WS2 64K | STAGE 2x32K | RED 4K
#define SC_WS1   0
#define SC_WS2   65536
#define SC_STAGE 131072
#define SC_RED   196608
#define SC_TOTAL 200704

__device__ __forceinline__ void stage_state(
    uint32_t sb, int buf, int c, int tid,
    const __nv_bfloat16* hi, const __nv_bfloat16* lo)
{
    uint32_t base = sb + SC_STAGE + buf * 32768;
    #pragma unroll
    for (int j = 0; j < 4; j++) {
        int q = tid + j * 256;               // < 1024
        int sub = q >> 9, m = (q >> 3) & 63, kg = q & 7;
        uint32_t d = sub * 8192 + SW128((uint32_t)(m * 128 + kg * 16));
        size_t src = (size_t)m * 1024 + c * 128 + sub * 64 + kg * 8;
        CPA(base + d,         hi + src);
        CPA(base + 16384 + d, lo + src);
    }
}

__device__ __forceinline__ void mma_chunk(
    uint32_t sb, uint32_t wsbase, int buf, int c,
    int lane, int mt, int kp, float acc[2][4])
{
    uint32_t sh = sb + SC_STAGE + buf * 32768 + kp * 8192;
    uint32_t sl = sh + 16384;
    uint32_t wh = sb + wsbase + (uint32_t)(c * 2 + kp) * 2048;
    uint32_t wl = wh + 32768;
    uint32_t aoff0 = (uint32_t)((mt * 16 + (lane & 15)) * 128 + (lane >> 4) * 16);
    uint32_t boff0 = (uint32_t)((((lane >> 4) << 3) + (lane & 7)) * 128 + ((lane >> 3) & 1) * 16);
    #pragma unroll
    for (int ks = 0; ks < 4; ks++) {
        uint32_t offA = SW128(aoff0 + ks * 32);
        uint32_t offB = SW128(boff0 + ks * 32);
        uint32_t ah[4], al[4], bh[4], bl[4];
        LDSM4(ah, sh + offA); LDSM4(al, sl + offA);
        LDSM4(bh, wh + offB); LDSM4(bl, wl + offB);
        MMA(acc[0], ah, bh); MMA(acc[0], ah, bl); MMA(acc[0], al, bh);
        MMA(acc[1], ah, bh + 2); MMA(acc[1], ah, bl + 2); MMA(acc[1], al, bh + 2);
    }
}

__global__ void __launch_bounds__(256, 1) k_scan() {
    extern __shared__ char sm[];
    const uint32_t sb = smem_u32(sm);
    float* redf = reinterpret_cast<float*>(sm + SC_RED);
    const int tid = threadIdx.x, lane = tid & 31, w = tid >> 5;
    const int g = blockIdx.x;
    const unsigned G = gridDim.x;
    const bool isZ = (g >= 64);
    const int n0p1 = (g & 63) * 16;
    const int n0p2 = g * 16;                 // blocks < 64
    const int mt = w & 3, kp = w >> 2;
    const int gg = lane >> 2, tg = lane & 3;

    // ---- load resident weights (bf16 hi/lo, swizzled, 16 sub-chunks of k64) ----
    {
        const __nv_bfloat16* Whi = g_wHhi + (size_t)(isZ ? 1 : 0) * (Hh * Hh) + (size_t)n0p1 * 1024;
        const __nv_bfloat16* Wlo = g_wHlo + (size_t)(isZ ? 1 : 0) * (Hh * Hh) + (size_t)n0p1 * 1024;
        #pragma unroll
        for (int j = 0; j < 8; j++) {
            int q = tid + j * 256;           // < 2048
            int sc = q >> 7, r = (q >> 3) & 15, kg = q & 7;
            uint32_t d = sc * 2048 + SW128((uint32_t)(r * 128 + kg * 16));
            size_t src = (size_t)r * 1024 + sc * 64 + kg * 8;
            CPA(sb + SC_WS1 + d,         Whi + src);
            CPA(sb + SC_WS1 + 32768 + d, Wlo + src);
        }
    }
    if (g < 64) {
        const __nv_bfloat16* Whi = g_wHhi + 2u * (Hh * Hh) + (size_t)n0p2 * 1024;
        const __nv_bfloat16* Wlo = g_wHlo + 2u * (Hh * Hh) + (size_t)n0p2 * 1024;
        #pragma unroll
        for (int j = 0; j < 8; j++) {
            int q = tid + j * 256;
            int sc = q >> 7, r = (q >> 3) & 15, kg = q & 7;
            uint32_t d = sc * 2048 + SW128((uint32_t)(r * 128 + kg * 16));
            size_t src = (size_t)r * 1024 + sc * 64 + kg * 8;
            CPA(sb + SC_WS2 + d,         Whi + src);
            CPA(sb + SC_WS2 + 32768 + d, Wlo + src);
        }
    }
    CP_COMMIT();
    CP_WAIT(0);
    __syncthreads();

    const float* pre1 = g_pre + (isZ ? (size_t)BT * Hh : 0);
    const float* pre2 = g_pre + 2 * (size_t)BT * Hh;

    for (int t = 0; t < Tt; t++) {
        // prefetch phase1 epilogue operands
        float2 pv[2][2], hv[2][2];
        if (w < 4) {
            #pragma unroll
            for (int nt = 0; nt < 2; nt++)
                #pragma unroll
                for (int rr = 0; rr < 2; rr++) {
                    int m = mt * 16 + gg + rr * 8;
                    int n = n0p1 + nt * 8 + tg * 2;
                    pv[nt][rr] = *reinterpret_cast<const float2*>(&pre1[(size_t)(m * Tt + t) * Hh + n]);
                    if (!isZ) hv[nt][rr] = *reinterpret_cast<const float2*>(&g_h[m * 1024 + n]);
                }
        }

        // ======== phase 1: r / z  (S = h @ W^T) ========
        float acc[2][4] = {};
        stage_state(sb, 0, 0, tid, g_shhi, g_shlo);
        CP_COMMIT();
        for (int c = 0; c < 8; c++) {
            if (c < 7) {
                stage_state(sb, (c + 1) & 1, c + 1, tid, g_shhi, g_shlo);
                CP_COMMIT();
                CP_WAIT(1);
            } else CP_WAIT(0);
            __syncthreads();
            mma_chunk(sb, SC_WS1, c & 1, c, lane, mt, kp, acc);
            __syncthreads();
        }
        // k-slice reduction (warps 4-7 -> warps 0-3)
        if (w >= 4) {
            #pragma unroll
            for (int nt = 0; nt < 2; nt++)
                #pragma unroll
                for (int i = 0; i < 4; i++)
                    redf[mt * 256 + lane * 8 + nt * 4 + i] = acc[nt][i];
        }
        __syncthreads();
        if (w < 4) {
            #pragma unroll
            for (int nt = 0; nt < 2; nt++) {
                #pragma unroll
                for (int i = 0; i < 4; i++)
                    acc[nt][i] += redf[mt * 256 + lane * 8 + nt * 4 + i];
                #pragma unroll
                for (int rr = 0; rr < 2; rr++) {
                    int m = mt * 16 + gg + rr * 8;
                    int n = n0p1 + nt * 8 + tg * 2;
                    float v0 = acc[nt][rr * 2 + 0] + pv[nt][rr].x;
                    float v1 = acc[nt][rr * 2 + 1] + pv[nt][rr].y;
                    float s0 = 1.f / (1.f + __expf(-v0));
                    float s1 = 1.f / (1.f + __expf(-v1));
                    if (!isZ) {
                        float rh0 = s0 * hv[nt][rr].x, rh1 = s1 * hv[nt][rr].y;
                        __nv_bfloat162 hi2, lo2;
                        split2(rh0, rh1, &hi2, &lo2);
                        *reinterpret_cast<__nv_bfloat162*>(&g_rhhi[m * 1024 + n]) = hi2;
                        *reinterpret_cast<__nv_bfloat162*>(&g_rhlo[m * 1024 + n]) = lo2;
                    } else {
                        *reinterpret_cast<float2*>(&g_zz[m * 1024 + n]) = make_float2(s0, s1);
                    }
                }
            }
        }
        gbarrier(2 * t, G);

        // ======== phase 2: hbar + state update (blocks 0-63) ========
        if (g < 64) {
            float2 pv2[2][2], zv[2][2], hpv[2][2];
            if (w < 4) {
                #pragma unroll
                for (int nt = 0; nt < 2; nt++)
                    #pragma unroll
                    for (int rr = 0; rr < 2; rr++) {
                        int m = mt * 16 + gg + rr * 8;
                        int n = n0p2 + nt * 8 + tg * 2;
                        pv2[nt][rr] = *reinterpret_cast<const float2*>(&pre2[(size_t)(m * Tt + t) * Hh + n]);
                        zv[nt][rr]  = *reinterpret_cast<const float2*>(&g_zz[m * 1024 + n]);
                        hpv[nt][rr] = *reinterpret_cast<const float2*>(&g_h[m * 1024 + n]);
                    }
            }
            float acc2[2][4] = {};
            stage_state(sb, 0, 0, tid, g_rhhi, g_rhlo);
            CP_COMMIT();
            for (int c = 0; c < 8; c++) {
                if (c < 7) {
                    stage_state(sb, (c + 1) & 1, c + 1, tid, g_rhhi, g_rhlo);
                    CP_COMMIT();
                    CP_WAIT(1);
                } else CP_WAIT(0);
                __syncthreads();
                mma_chunk(sb, SC_WS2, c & 1, c, lane, mt, kp, acc2);
                __syncthreads();
            }
            if (w >= 4) {
                #pragma unroll
                for (int nt = 0; nt < 2; nt++)
                    #pragma unroll
                    for (int i = 0; i < 4; i++)
                        redf[mt * 256 + lane * 8 + nt * 4 + i] = acc2[nt][i];
            }
            __syncthreads();
            if (w < 4) {
                #pragma unroll
                for (int nt = 0; nt < 2; nt++) {
                    #pragma unroll
                    for (int i = 0; i < 4; i++)
                        acc2[nt][i] += redf[mt * 256 + lane * 8 + nt * 4 + i];
                    #pragma unroll
                    for (int rr = 0; rr < 2; rr++) {
                        int m = mt * 16 + gg + rr * 8;
                        int n = n0p2 + nt * 8 + tg * 2;
                        float hb0 = tanhf(acc2[nt][rr * 2 + 0] + pv2[nt][rr].x);
                        float hb1 = tanhf(acc2[nt][rr * 2 + 1] + pv2[nt][rr].y);
                        float hn0 = fmaf(zv[nt][rr].x, hb0 - hpv[nt][rr].x, hpv[nt][rr].x);
                        float hn1 = fmaf(zv[nt][rr].y, hb1 - hpv[nt][rr].y, hpv[nt][rr].y);
                        *reinterpret_cast<float2*>(&g_h[m * 1024 + n]) = make_float2(hn0, hn1);
                        __nv_bfloat162 hi2, lo2;
                        split2(hn0, hn1, &hi2, &lo2);
                        *reinterpret_cast<__nv_bfloat162*>(&g_shhi[m * 1024 + n]) = hi2;
                        *reinterpret_cast<__nv_bfloat162*>(&g_shlo[m * 1024 + n]) = lo2;
                        size_t ho = (size_t)(m * Tt + t) * Hh + n;
                        *reinterpret_cast<__nv_bfloat162*>(&g_hhi[ho]) = hi2;
                        *reinterpret_cast<__nv_bfloat162*>(&g_hlo[ho]) = lo2;
                    }
                }
            }
        }
        gbarrier(2 * t + 1, G);
    }
}

// ---------------- launch ----------------
extern "C" void kernel_launch(void* const* d_in, const int* in_sizes, int n_in,
                              void* d_out, int out_size)
{
    const int*   x     = (const int*)  d_in[0];
    const float* start = (const float*)d_in[1];
    const float* wte   = (const float*)d_in[2];
    const float* Wr    = (const float*)d_in[3];
    const float* br    = (const float*)d_in[4];
    const float* Wbar  = (const float*)d_in[5];
    const float* bbar  = (const float*)d_in[6];
    const float* Wz    = (const float*)d_in[7];
    const float* bz    = (const float*)d_in[8];
    const float* Whead = (const float*)d_in[9];
    const float* bhead = (const float*)d_in[10];
    float* out = (float*)d_out;

    float* p_pre;
    __nv_bfloat16 *p_ehi, *p_elo, *p_hhi, *p_hlo, *p_wchi, *p_wclo, *p_whhi, *p_whlo;
    cudaGetSymbolAddress((void**)&p_pre,  g_pre);
    cudaGetSymbolAddress((void**)&p_ehi,  g_ehi);   cudaGetSymbolAddress((void**)&p_elo,  g_elo);
    cudaGetSymbolAddress((void**)&p_hhi,  g_hhi);   cudaGetSymbolAddress((void**)&p_hlo,  g_hlo);
    cudaGetSymbolAddress((void**)&p_wchi, g_wchi);  cudaGetSymbolAddress((void**)&p_wclo, g_wclo);
    cudaGetSymbolAddress((void**)&p_whhi, g_whhi);  cudaGetSymbolAddress((void**)&p_whlo, g_whlo);

    cudaFuncSetAttribute(k_scan,  cudaFuncAttributeMaxDynamicSharedMemorySize, SC_TOTAL);
    cudaFuncSetAttribute(k_tgemm, cudaFuncAttributeMaxDynamicSharedMemorySize, SM_TOTAL);

    k_init<<<256, 256>>>(start);
    k_embed<<<(BT * Ee / 4) / 256, 256>>>(x, wte);
    k_cvt_wcat<<<(3 * Hh * Ee) / 256, 256>>>(Wr, Wz, Wbar);
    k_cvt_wH<<<(3 * Hh * Hh) / 256, 256>>>(Wr, Wz, Wbar);
    k_cvt<<<(Vv * Hh / 4) / 256, 256>>>(Whead, p_whhi, p_whlo);

    // pre-projections: 3 gates, N=1024 each, K=512
    for (int gate = 0; gate < 3; gate++) {
        const float* bias = (gate == 0) ? br : (gate == 1) ? bz : bbar;
        k_tgemm<<<dim3(Hh/128, BT/128), 256, SM_TOTAL>>>(
            p_ehi, p_elo,
            p_wchi + (size_t)gate * Hh * Ee, p_wclo + (size_t)gate * Hh * Ee,
            bias, p_pre + (size_t)gate * BT * Hh, Ee, Hh, Ee/64);
    }

    k_scan<<<128, 256, SC_TOTAL>>>();

    k_tgemm<<<dim3(Vv/128, BT/128), 256, SM_TOTAL>>>(
        p_hhi, p_hlo, p_whhi, p_whlo, bhead, out, Hh, Vv, Hh/64);
}

// round 7
// speedup vs baseline: 12.6151x; 1.1848x over previous
#include <cuda_runtime.h>
#include <cuda_bf16.h>
#include <math.h>
#include <stdint.h>

#define Bz   64
#define Tt   256
#define Vv   4096
#define Ee   512
#define Hh   1024
#define BT   (Bz*Tt)
#define CAT  (Ee+Hh)

// ---------------- static device scratch ----------------
__device__ float          g_pre[3u * BT * Hh];     // [gate][bt][n] gate 0=r,1=z,2=hbar
__device__ float          g_h[Bz * Hh];            // fp32 state [m][n]
__device__ float          g_zz[Bz * Hh];           // z [m][n]
__device__ __nv_bfloat16  g_shhi[Bz * Hh];         // state hi/lo [m][k]
__device__ __nv_bfloat16  g_shlo[Bz * Hh];
__device__ __nv_bfloat16  g_rhhi[Bz * Hh];         // r*h hi/lo [m][k]
__device__ __nv_bfloat16  g_rhlo[Bz * Hh];
__device__ unsigned       g_bar[1024];
__device__ __nv_bfloat16  g_ehi[BT * Ee];
__device__ __nv_bfloat16  g_elo[BT * Ee];
__device__ __nv_bfloat16  g_hhi[BT * Hh];          // hidden (head input) [bt][k]
__device__ __nv_bfloat16  g_hlo[BT * Hh];
__device__ __nv_bfloat16  g_wchi[3 * Hh * Ee];     // gate weights E-part [3072][512]
__device__ __nv_bfloat16  g_wclo[3 * Hh * Ee];
__device__ __nv_bfloat16  g_wHhi[3u * Hh * Hh];    // gate weights H-part [3][1024][1024]
__device__ __nv_bfloat16  g_wHlo[3u * Hh * Hh];
__device__ __nv_bfloat16  g_whhi[Vv * Hh];
__device__ __nv_bfloat16  g_whlo[Vv * Hh];

// ---------------- helpers ----------------
__device__ __forceinline__ uint32_t smem_u32(const void* p) {
    uint32_t a;
    asm("{ .reg .u64 t; cvta.to.shared.u64 t, %1; cvt.u32.u64 %0, t; }" : "=r"(a) : "l"(p));
    return a;
}
#define CP_COMMIT() asm volatile("cp.async.commit_group;" ::: "memory")
#define CP_WAIT(n)  asm volatile("cp.async.wait_group %0;" :: "n"(n) : "memory")
#define CPA(dst, src) \
    asm volatile("cp.async.cg.shared.global [%0], [%1], 16;" :: "r"(dst), "l"(src) : "memory")
#define SW128(x) ((x) ^ (((x) >> 3) & 0x70))

#define LDSM4(r, addr) \
    asm volatile("ldmatrix.sync.aligned.m8n8.x4.shared.b16 {%0,%1,%2,%3}, [%4];" \
        : "=r"((r)[0]), "=r"((r)[1]), "=r"((r)[2]), "=r"((r)[3]) : "r"(addr))

#define MMA(d, a, b) \
    asm volatile("mma.sync.aligned.m16n8k16.row.col.f32.bf16.bf16.f32 " \
        "{%0,%1,%2,%3}, {%4,%5,%6,%7}, {%8,%9}, {%0,%1,%2,%3};" \
        : "+f"((d)[0]), "+f"((d)[1]), "+f"((d)[2]), "+f"((d)[3]) \
        : "r"((a)[0]), "r"((a)[1]), "r"((a)[2]), "r"((a)[3]), "r"((b)[0]), "r"((b)[1]))

__device__ __forceinline__ void split2(float a, float b, __nv_bfloat162* hi, __nv_bfloat162* lo) {
    __nv_bfloat16 ah = __float2bfloat16(a), bh = __float2bfloat16(b);
    *hi = __nv_bfloat162(ah, bh);
    *lo = __nv_bfloat162(__float2bfloat16(a - __bfloat162float(ah)),
                         __float2bfloat16(b - __bfloat162float(bh)));
}

// ---------------- init / embed / converters ----------------
__global__ void k_init(const float* __restrict__ start) {
    int i = blockIdx.x * blockDim.x + threadIdx.x;   // 65536
    float v = start[i & 1023];
    g_h[i] = v;
    __nv_bfloat16 h = __float2bfloat16(v);
    g_shhi[i] = h;
    g_shlo[i] = __float2bfloat16(v - __bfloat162float(h));
    if (i < 1024) g_bar[i] = 0u;
}
__global__ void k_embed(const int* __restrict__ x, const float* __restrict__ wte) {
    int i  = blockIdx.x * blockDim.x + threadIdx.x;
    int bt = i >> 7, e4 = i & 127;
    int tok = x[bt];
    float4 v = reinterpret_cast<const float4*>(wte + (size_t)tok * Ee)[e4];
    __nv_bfloat162 h0, l0, h1, l1;
    split2(v.x, v.y, &h0, &l0); split2(v.z, v.w, &h1, &l1);
    reinterpret_cast<__nv_bfloat162*>(g_ehi)[2*i]   = h0;
    reinterpret_cast<__nv_bfloat162*>(g_ehi)[2*i+1] = h1;
    reinterpret_cast<__nv_bfloat162*>(g_elo)[2*i]   = l0;
    reinterpret_cast<__nv_bfloat162*>(g_elo)[2*i+1] = l1;
}
__global__ void k_cvt(const float* __restrict__ src, __nv_bfloat16* __restrict__ hi,
                      __nv_bfloat16* __restrict__ lo) {
    int i = blockIdx.x * blockDim.x + threadIdx.x;
    float4 v = reinterpret_cast<const float4*>(src)[i];
    __nv_bfloat162 h0, l0, h1, l1;
    split2(v.x, v.y, &h0, &l0); split2(v.z, v.w, &h1, &l1);
    reinterpret_cast<__nv_bfloat162*>(hi)[2*i]   = h0;
    reinterpret_cast<__nv_bfloat162*>(hi)[2*i+1] = h1;
    reinterpret_cast<__nv_bfloat162*>(lo)[2*i]   = l0;
    reinterpret_cast<__nv_bfloat162*>(lo)[2*i+1] = l1;
}
__global__ void k_cvt_wcat(const float* __restrict__ Wr, const float* __restrict__ Wz,
                           const float* __restrict__ Wbar) {
    int i = blockIdx.x * blockDim.x + threadIdx.x;    // 3072*512
    int row = i >> 9, col = i & 511;
    const float* W = (row < 1024) ? Wr : (row < 2048) ? Wz : Wbar;
    float v = W[(size_t)(row & 1023) * CAT + col];
    __nv_bfloat16 h = __float2bfloat16(v);
    g_wchi[i] = h;
    g_wclo[i] = __float2bfloat16(v - __bfloat162float(h));
}
__global__ void k_cvt_wH(const float* __restrict__ Wr, const float* __restrict__ Wz,
                         const float* __restrict__ Wbar) {
    int i = blockIdx.x * blockDim.x + threadIdx.x;    // 3*1024*1024
    int gate = i >> 20, row = (i >> 10) & 1023, col = i & 1023;
    const float* W = (gate == 0) ? Wr : (gate == 1) ? Wz : Wbar;
    float v = W[(size_t)row * CAT + Ee + col];
    __nv_bfloat16 h = __float2bfloat16(v);
    g_wHhi[i] = h;
    g_wHlo[i] = __float2bfloat16(v - __bfloat162float(h));
}

// ---------------- split-bf16 HMMA GEMM (pre-projections + head) ----------------
#define STG      65536
#define SOFF_ALO 16384
#define SOFF_BHI 32768
#define SOFF_BLO 49152
#define SM_TOTAL 131072

__device__ __forceinline__ void load_chunk(
    uint32_t sb, int s, int tid,
    const __nv_bfloat16* Ahi, const __nv_bfloat16* Alo,
    const __nv_bfloat16* Bhi, const __nv_bfloat16* Blo,
    int m0, int n0, int kc, int K)
{
    uint32_t st = sb + s * STG;
    int kb = kc * 64;
    #pragma unroll
    for (int j = 0; j < 4; j++) {
        int q = tid + j * 256, row = q >> 3, kg = q & 7;
        uint32_t d = SW128((uint32_t)(row * 128 + kg * 16));
        size_t srcA = (size_t)(m0 + row) * K + kb + kg * 8;
        size_t srcB = (size_t)(n0 + row) * K + kb + kg * 8;
        CPA(st + d,            Ahi + srcA);
        CPA(st + SOFF_ALO + d, Alo + srcA);
        CPA(st + SOFF_BHI + d, Bhi + srcB);
        CPA(st + SOFF_BLO + d, Blo + srcB);
    }
}

__global__ void __launch_bounds__(256, 1) k_tgemm(
    const __nv_bfloat16* __restrict__ Ahi, const __nv_bfloat16* __restrict__ Alo,
    const __nv_bfloat16* __restrict__ Bhi, const __nv_bfloat16* __restrict__ Blo,
    const float* __restrict__ bias, float* __restrict__ C, int K, int ldc, int nk)
{
    extern __shared__ char smem[];
    const uint32_t sb = smem_u32(smem);
    const int tid = threadIdx.x, lane = tid & 31, wid = tid >> 5;
    const int wm = wid & 3, wn = wid >> 2;
    const int m0 = blockIdx.y * 128, n0 = blockIdx.x * 128;

    float acc[2][8][4] = {};

    load_chunk(sb, 0, tid, Ahi, Alo, Bhi, Blo, m0, n0, 0, K);
    CP_COMMIT();

    for (int kc = 0; kc < nk; kc++) {
        if (kc + 1 < nk) {
            load_chunk(sb, (kc + 1) & 1, tid, Ahi, Alo, Bhi, Blo, m0, n0, kc + 1, K);
            CP_COMMIT();
            CP_WAIT(1);
        } else {
            CP_WAIT(0);
        }
        __syncthreads();

        const uint32_t st = sb + (kc & 1) * STG;
        #pragma unroll
        for (int ks = 0; ks < 4; ks++) {
            uint32_t a_hi[2][4], a_lo[2][4];
            {
                int acol = ks * 32 + (lane >> 4) * 16;
                #pragma unroll
                for (int mt = 0; mt < 2; mt++) {
                    int arow = wm * 32 + mt * 16 + (lane & 15);
                    uint32_t off = SW128((uint32_t)(arow * 128 + acol));
                    LDSM4(a_hi[mt], st + off);
                    LDSM4(a_lo[mt], st + SOFF_ALO + off);
                }
            }
            uint32_t b_hi[8][2], b_lo[8][2];
            {
                int bcol  = ks * 32 + ((lane >> 3) & 1) * 16;
                int brofs = (lane >> 4) * 8 + (lane & 7);
                #pragma unroll
                for (int nt2 = 0; nt2 < 4; nt2++) {
                    int brow = wn * 64 + nt2 * 16 + brofs;
                    uint32_t off = SW128((uint32_t)(brow * 128 + bcol));
                    uint32_t r[4];
                    LDSM4(r, st + SOFF_BHI + off);
                    b_hi[nt2*2][0]   = r[0]; b_hi[nt2*2][1]   = r[1];
                    b_hi[nt2*2+1][0] = r[2]; b_hi[nt2*2+1][1] = r[3];
                    LDSM4(r, st + SOFF_BLO + off);
                    b_lo[nt2*2][0]   = r[0]; b_lo[nt2*2][1]   = r[1];
                    b_lo[nt2*2+1][0] = r[2]; b_lo[nt2*2+1][1] = r[3];
                }
            }
            #pragma unroll
            for (int mt = 0; mt < 2; mt++)
                #pragma unroll
                for (int nt = 0; nt < 8; nt++) {
                    MMA(acc[mt][nt], a_hi[mt], b_hi[nt]);
                    MMA(acc[mt][nt], a_hi[mt], b_lo[nt]);
                    MMA(acc[mt][nt], a_lo[mt], b_hi[nt]);
                }
        }
        __syncthreads();
    }

    const int g = lane >> 2, tg = lane & 3;
    #pragma unroll
    for (int nt = 0; nt < 8; nt++) {
        int col = n0 + wn * 64 + nt * 8 + tg * 2;
        float b0 = bias[col], b1 = bias[col + 1];
        #pragma unroll
        for (int mt = 0; mt < 2; mt++) {
            int r0 = m0 + wm * 32 + mt * 16 + g;
            float2 v0 = make_float2(acc[mt][nt][0] + b0, acc[mt][nt][1] + b1);
            float2 v1 = make_float2(acc[mt][nt][2] + b0, acc[mt][nt][3] + b1);
            *reinterpret_cast<float2*>(C + (size_t)r0 * ldc + col)       = v0;
            *reinterpret_cast<float2*>(C + (size_t)(r0 + 8) * ldc + col) = v1;
        }
    }
}

// ---------------- grid barrier ----------------
__device__ __forceinline__ void gbarrier(int idx, unsigned G) {
    __syncthreads();
    if (threadIdx.x == 0) {
        __threadfence();
        unsigned a = atomicAdd(&g_bar[idx], 1u);
        if (a + 1u < G)
            while (*reinterpret_cast<volatile unsigned*>(&g_bar[idx]) < G) __nanosleep(32);
        __threadfence();
    }
    __syncthreads();
}

// ---------------- HMMA persistent scan ----------------
// 128 blocks x 256 threads. smem: WS1 64K | WS2 64K | STAGE 3x32K (RED aliased)
#define SC_WS1   0
#define SC_WS2   65536
#define SC_STAGE 131072
#define SC_TOTAL 229376

// phase1 staging: 64 rows x k128 chunk (hi 16K + lo 16K) into 32K buffer
__device__ __forceinline__ void stage1(uint32_t sb, int c, int tid,
                                       const __nv_bfloat16* hi, const __nv_bfloat16* lo)
{
    uint32_t base = sb + SC_STAGE + (uint32_t)(c % 3) * 32768;
    #pragma unroll
    for (int j = 0; j < 4; j++) {
        int q = tid + j * 256;               // < 1024
        int sub = q >> 9, m = (q >> 3) & 63, kg = q & 7;
        uint32_t d = sub * 8192 + SW128((uint32_t)(m * 128 + kg * 16));
        size_t src = (size_t)m * 1024 + c * 128 + sub * 64 + kg * 8;
        CPA(base + d,         hi + src);
        CPA(base + 16384 + d, lo + src);
    }
}

// phase2 staging: 32 rows (m-half mh) x k128 chunk (hi 8K + lo 8K) into 16K buffer
__device__ __forceinline__ void stage2(uint32_t sb, int c, int tid, int mh,
                                       const __nv_bfloat16* hi, const __nv_bfloat16* lo)
{
    uint32_t base = sb + SC_STAGE + (uint32_t)(c % 3) * 16384;
    #pragma unroll
    for (int j = 0; j < 2; j++) {
        int q = tid + j * 256;               // < 512
        int sub = q >> 8, m = (q >> 3) & 31, kg = q & 7;
        uint32_t d = sub * 4096 + SW128((uint32_t)(m * 128 + kg * 16));
        size_t src = (size_t)(mh * 32 + m) * 1024 + c * 128 + sub * 64 + kg * 8;
        CPA(base + d,        hi + src);
        CPA(base + 8192 + d, lo + src);
    }
}

__device__ __forceinline__ void mma_chunk1(uint32_t sb, int c, int lane, int mt, int kp,
                                           float acc[2][4])
{
    uint32_t sh = sb + SC_STAGE + (uint32_t)(c % 3) * 32768 + kp * 8192;
    uint32_t sl = sh + 16384;
    uint32_t wh = sb + SC_WS1 + (uint32_t)(c * 2 + kp) * 2048;
    uint32_t wl = wh + 32768;
    uint32_t aoff0 = (uint32_t)((mt * 16 + (lane & 15)) * 128 + (lane >> 4) * 16);
    uint32_t boff0 = (uint32_t)((((lane >> 4) << 3) + (lane & 7)) * 128 + ((lane >> 3) & 1) * 16);
    #pragma unroll
    for (int ks = 0; ks < 4; ks++) {
        uint32_t offA = SW128(aoff0 + ks * 32);
        uint32_t offB = SW128(boff0 + ks * 32);
        uint32_t ah[4], al[4], bh[4], bl[4];
        LDSM4(ah, sh + offA); LDSM4(al, sl + offA);
        LDSM4(bh, wh + offB); LDSM4(bl, wl + offB);
        MMA(acc[0], ah, bh); MMA(acc[0], ah, bl); MMA(acc[0], al, bh);
        MMA(acc[1], ah, bh + 2); MMA(acc[1], ah, bl + 2); MMA(acc[1], al, bh + 2);
    }
}

__device__ __forceinline__ void mma_chunk2(uint32_t sb, int c, int lane, int mt2, int kq,
                                           float acc[2][4])
{
    uint32_t sh = sb + SC_STAGE + (uint32_t)(c % 3) * 16384 + (kq >> 1) * 4096;
    uint32_t sl = sh + 8192;
    uint32_t wh = sb + SC_WS2 + (uint32_t)(c * 2 + (kq >> 1)) * 2048;
    uint32_t wl = wh + 32768;
    uint32_t aoff0 = (uint32_t)((mt2 * 16 + (lane & 15)) * 128 + (lane >> 4) * 16 + (kq & 1) * 64);
    uint32_t boff0 = (uint32_t)((((lane >> 4) << 3) + (lane & 7)) * 128
                              + ((lane >> 3) & 1) * 16 + (kq & 1) * 64);
    #pragma unroll
    for (int ks = 0; ks < 2; ks++) {
        uint32_t offA = SW128(aoff0 + ks * 32);
        uint32_t offB = SW128(boff0 + ks * 32);
        uint32_t ah[4], al[4], bh[4], bl[4];
        LDSM4(ah, sh + offA); LDSM4(al, sl + offA);
        LDSM4(bh, wh + offB); LDSM4(bl, wl + offB);
        MMA(acc[0], ah, bh); MMA(acc[0], ah, bl); MMA(acc[0], al, bh);
        MMA(acc[1], ah, bh + 2); MMA(acc[1], ah, bl + 2); MMA(acc[1], al, bh + 2);
    }
}

__global__ void __launch_bounds__(256, 1) k_scan() {
    extern __shared__ char sm[];
    const uint32_t sb = smem_u32(sm);
    float* redf = reinterpret_cast<float*>(sm + SC_STAGE);   // aliased over stage buf0
    const int tid = threadIdx.x, lane = tid & 31, w = tid >> 5;
    const int g = blockIdx.x;
    const unsigned G = gridDim.x;
    const bool isZ = (g >= 64);
    const int n0p1 = (g & 63) * 16;
    const int mh   = isZ ? 1 : 0;            // phase2 m-half
    const int n0p2 = (g & 63) * 16;          // phase2 n-cols
    const int mt = w & 3, kp = w >> 2;       // phase1: 4 m-tiles x 2 k-halves
    const int mt2 = w & 1, kq = w >> 1;      // phase2: 2 m-tiles x 4 k-quarters
    const int gg = lane >> 2, tg = lane & 3;

    // ---- resident weights ----
    {
        const __nv_bfloat16* Whi = g_wHhi + (size_t)(isZ ? 1 : 0) * (Hh * Hh) + (size_t)n0p1 * 1024;
        const __nv_bfloat16* Wlo = g_wHlo + (size_t)(isZ ? 1 : 0) * (Hh * Hh) + (size_t)n0p1 * 1024;
        #pragma unroll
        for (int j = 0; j < 8; j++) {
            int q = tid + j * 256;           // < 2048
            int sc = q >> 7, r = (q >> 3) & 15, kg = q & 7;
            uint32_t d = sc * 2048 + SW128((uint32_t)(r * 128 + kg * 16));
            size_t src = (size_t)r * 1024 + sc * 64 + kg * 8;
            CPA(sb + SC_WS1 + d,         Whi + src);
            CPA(sb + SC_WS1 + 32768 + d, Wlo + src);
        }
    }
    {
        const __nv_bfloat16* Whi = g_wHhi + 2u * (Hh * Hh) + (size_t)n0p2 * 1024;
        const __nv_bfloat16* Wlo = g_wHlo + 2u * (Hh * Hh) + (size_t)n0p2 * 1024;
        #pragma unroll
        for (int j = 0; j < 8; j++) {
            int q = tid + j * 256;
            int sc = q >> 7, r = (q >> 3) & 15, kg = q & 7;
            uint32_t d = sc * 2048 + SW128((uint32_t)(r * 128 + kg * 16));
            size_t src = (size_t)r * 1024 + sc * 64 + kg * 8;
            CPA(sb + SC_WS2 + d,         Whi + src);
            CPA(sb + SC_WS2 + 32768 + d, Wlo + src);
        }
    }
    CP_COMMIT();
    CP_WAIT(0);
    __syncthreads();

    const float* pre1 = g_pre + (isZ ? (size_t)BT * Hh : 0);
    const float* pre2 = g_pre + 2 * (size_t)BT * Hh;

    for (int t = 0; t < Tt; t++) {
        // prefetch phase1 epilogue operands
        float2 pv[2][2], hv[2][2];
        if (w < 4) {
            #pragma unroll
            for (int nt = 0; nt < 2; nt++)
                #pragma unroll
                for (int rr = 0; rr < 2; rr++) {
                    int m = mt * 16 + gg + rr * 8;
                    int n = n0p1 + nt * 8 + tg * 2;
                    pv[nt][rr] = *reinterpret_cast<const float2*>(&pre1[(size_t)(m * Tt + t) * Hh + n]);
                    if (!isZ) hv[nt][rr] = *reinterpret_cast<const float2*>(&g_h[m * 1024 + n]);
                }
        }

        // ======== phase 1: r / z (S = h @ W^T), 64 rows ========
        float acc[2][4] = {};
        stage1(sb, 0, tid, g_shhi, g_shlo); CP_COMMIT();
        stage1(sb, 1, tid, g_shhi, g_shlo); CP_COMMIT();
        for (int c = 0; c < 8; c++) {
            if (c + 2 < 8) { CP_WAIT(1); } else { CP_WAIT(0); }
            __syncthreads();
            if (c + 2 < 8) { stage1(sb, c + 2, tid, g_shhi, g_shlo); CP_COMMIT(); }
            mma_chunk1(sb, c, lane, mt, kp, acc);
        }
        __syncthreads();                      // all reads done before red (aliased buf0) write
        if (w >= 4) {
            #pragma unroll
            for (int nt = 0; nt < 2; nt++)
                #pragma unroll
                for (int i = 0; i < 4; i++)
                    redf[mt * 256 + lane * 8 + nt * 4 + i] = acc[nt][i];
        }
        __syncthreads();
        if (w < 4) {
            #pragma unroll
            for (int nt = 0; nt < 2; nt++) {
                #pragma unroll
                for (int i = 0; i < 4; i++)
                    acc[nt][i] += redf[mt * 256 + lane * 8 + nt * 4 + i];
                #pragma unroll
                for (int rr = 0; rr < 2; rr++) {
                    int m = mt * 16 + gg + rr * 8;
                    int n = n0p1 + nt * 8 + tg * 2;
                    float v0 = acc[nt][rr * 2 + 0] + pv[nt][rr].x;
                    float v1 = acc[nt][rr * 2 + 1] + pv[nt][rr].y;
                    float s0 = 1.f / (1.f + __expf(-v0));
                    float s1 = 1.f / (1.f + __expf(-v1));
                    if (!isZ) {
                        float rh0 = s0 * hv[nt][rr].x, rh1 = s1 * hv[nt][rr].y;
                        __nv_bfloat162 hi2, lo2;
                        split2(rh0, rh1, &hi2, &lo2);
                        *reinterpret_cast<__nv_bfloat162*>(&g_rhhi[m * 1024 + n]) = hi2;
                        *reinterpret_cast<__nv_bfloat162*>(&g_rhlo[m * 1024 + n]) = lo2;
                    } else {
                        *reinterpret_cast<float2*>(&g_zz[m * 1024 + n]) = make_float2(s0, s1);
                    }
                }
            }
        }
        gbarrier(2 * t, G);

        // ======== phase 2: hbar + update, 32 rows (m-half), all 128 blocks ========
        {
            float2 pv2[2][2], zv[2][2], hpv[2][2];
            if (w < 2) {
                #pragma unroll
                for (int nt = 0; nt < 2; nt++)
                    #pragma unroll
                    for (int rr = 0; rr < 2; rr++) {
                        int m = mh * 32 + mt2 * 16 + gg + rr * 8;
                        int n = n0p2 + nt * 8 + tg * 2;
                        pv2[nt][rr] = *reinterpret_cast<const float2*>(&pre2[(size_t)(m * Tt + t) * Hh + n]);
                        zv[nt][rr]  = *reinterpret_cast<const float2*>(&g_zz[m * 1024 + n]);
                        hpv[nt][rr] = *reinterpret_cast<const float2*>(&g_h[m * 1024 + n]);
                    }
            }
            float acc2[2][4] = {};
            stage2(sb, 0, tid, mh, g_rhhi, g_rhlo); CP_COMMIT();
            stage2(sb, 1, tid, mh, g_rhhi, g_rhlo); CP_COMMIT();
            for (int c = 0; c < 8; c++) {
                if (c + 2 < 8) { CP_WAIT(1); } else { CP_WAIT(0); }
                __syncthreads();
                if (c + 2 < 8) { stage2(sb, c + 2, tid, mh, g_rhhi, g_rhlo); CP_COMMIT(); }
                mma_chunk2(sb, c, lane, mt2, kq, acc2);
            }
            __syncthreads();
            if (kq > 0) {                     // warps 2-7 write partials
                int slot = (kq - 1) * 2 + mt2;
                #pragma unroll
                for (int nt = 0; nt < 2; nt++)
                    #pragma unroll
                    for (int i = 0; i < 4; i++)
                        redf[slot * 256 + lane * 8 + nt * 4 + i] = acc2[nt][i];
            }
            __syncthreads();
            if (w < 2) {
                #pragma unroll
                for (int q = 0; q < 3; q++)
                    #pragma unroll
                    for (int nt = 0; nt < 2; nt++)
                        #pragma unroll
                        for (int i = 0; i < 4; i++)
                            acc2[nt][i] += redf[(q * 2 + mt2) * 256 + lane * 8 + nt * 4 + i];
                #pragma unroll
                for (int nt = 0; nt < 2; nt++) {
                    #pragma unroll
                    for (int rr = 0; rr < 2; rr++) {
                        int m = mh * 32 + mt2 * 16 + gg + rr * 8;
                        int n = n0p2 + nt * 8 + tg * 2;
                        float hb0 = tanhf(acc2[nt][rr * 2 + 0] + pv2[nt][rr].x);
                        float hb1 = tanhf(acc2[nt][rr * 2 + 1] + pv2[nt][rr].y);
                        float hn0 = fmaf(zv[nt][rr].x, hb0 - hpv[nt][rr].x, hpv[nt][rr].x);
                        float hn1 = fmaf(zv[nt][rr].y, hb1 - hpv[nt][rr].y, hpv[nt][rr].y);
                        *reinterpret_cast<float2*>(&g_h[m * 1024 + n]) = make_float2(hn0, hn1);
                        __nv_bfloat162 hi2, lo2;
                        split2(hn0, hn1, &hi2, &lo2);
                        *reinterpret_cast<__nv_bfloat162*>(&g_shhi[m * 1024 + n]) = hi2;
                        *reinterpret_cast<__nv_bfloat162*>(&g_shlo[m * 1024 + n]) = lo2;
                        size_t ho = (size_t)(m * Tt + t) * Hh + n;
                        *reinterpret_cast<__nv_bfloat162*>(&g_hhi[ho]) = hi2;
                        *reinterpret_cast<__nv_bfloat162*>(&g_hlo[ho]) = lo2;
                    }
                }
            }
        }
        gbarrier(2 * t + 1, G);
    }
}

// ---------------- launch ----------------
extern "C" void kernel_launch(void* const* d_in, const int* in_sizes, int n_in,
                              void* d_out, int out_size)
{
    const int*   x     = (const int*)  d_in[0];
    const float* start = (const float*)d_in[1];
    const float* wte   = (const float*)d_in[2];
    const float* Wr    = (const float*)d_in[3];
    const float* br    = (const float*)d_in[4];
    const float* Wbar  = (const float*)d_in[5];
    const float* bbar  = (const float*)d_in[6];
    const float* Wz    = (const float*)d_in[7];
    const float* bz    = (const float*)d_in[8];
    const float* Whead = (const float*)d_in[9];
    const float* bhead = (const float*)d_in[10];
    float* out = (float*)d_out;

    float* p_pre;
    __nv_bfloat16 *p_ehi, *p_elo, *p_hhi, *p_hlo, *p_wchi, *p_wclo, *p_whhi, *p_whlo;
    cudaGetSymbolAddress((void**)&p_pre,  g_pre);
    cudaGetSymbolAddress((void**)&p_ehi,  g_ehi);   cudaGetSymbolAddress((void**)&p_elo,  g_elo);
    cudaGetSymbolAddress((void**)&p_hhi,  g_hhi);   cudaGetSymbolAddress((void**)&p_hlo,  g_hlo);
    cudaGetSymbolAddress((void**)&p_wchi, g_wchi);  cudaGetSymbolAddress((void**)&p_wclo, g_wclo);
    cudaGetSymbolAddress((void**)&p_whhi, g_whhi);  cudaGetSymbolAddress((void**)&p_whlo, g_whlo);

    cudaFuncSetAttribute(k_scan,  cudaFuncAttributeMaxDynamicSharedMemorySize, SC_TOTAL);
    cudaFuncSetAttribute(k_tgemm, cudaFuncAttributeMaxDynamicSharedMemorySize, SM_TOTAL);

    k_init<<<256, 256>>>(start);
    k_embed<<<(BT * Ee / 4) / 256, 256>>>(x, wte);
    k_cvt_wcat<<<(3 * Hh * Ee) / 256, 256>>>(Wr, Wz, Wbar);
    k_cvt_wH<<<(3 * Hh * Hh) / 256, 256>>>(Wr, Wz, Wbar);
    k_cvt<<<(Vv * Hh / 4) / 256, 256>>>(Whead, p_whhi, p_whlo);

    // pre-projections: 3 gates, N=1024 each, K=512
    for (int gate = 0; gate < 3; gate++) {
        const float* bias = (gate == 0) ? br : (gate == 1) ? bz : bbar;
        k_tgemm<<<dim3(Hh/128, BT/128), 256, SM_TOTAL>>>(
            p_ehi, p_elo,
            p_wchi + (size_t)gate * Hh * Ee, p_wclo + (size_t)gate * Hh * Ee,
            bias, p_pre + (size_t)gate * BT * Hh, Ee, Hh, Ee/64);
    }

    k_scan<<<128, 256, SC_TOTAL>>>();

    k_tgemm<<<dim3(Vv/128, BT/128), 256, SM_TOTAL>>>(
        p_hhi, p_hlo, p_whhi, p_whlo, bhead, out, Hh, Vv, Hh/64);
}